// round 8
// baseline (speedup 1.0000x reference)
#include <cuda_runtime.h>
#include <cuda_bf16.h>

#define DD 128
#define MAXN 50176   // >= N, multiple of 128

// ---------------- scratch (static __device__; allocation-free) ----------------
__device__ __align__(16) int   g_cnt[MAXN];
__device__ __align__(16) float g_inv[MAXN];
__device__ __align__(16) float g_neigh[MAXN * DD];
__device__ __align__(16) float g_conv [MAXN * DD];
__device__ __align__(16) float g_m    [MAXN * DD];
__device__ __align__(16) float g_std  [MAXN * DD];
__device__ __align__(16) float g_tmp  [MAXN * DD];

// ---------------- helpers ----------------
__device__ __forceinline__ void red_add_v4(float* p, float4 v) {
    asm volatile("red.global.add.v4.f32 [%0], {%1,%2,%3,%4};"
                 :: "l"(p), "f"(v.x), "f"(v.y), "f"(v.z), "f"(v.w) : "memory");
}

// ---------------- zero scratch accumulators ----------------
__global__ void zero_k(int n4_big, int n4_cnt) {
    int i = blockIdx.x * blockDim.x + threadIdx.x;
    float4 z = make_float4(0.f, 0.f, 0.f, 0.f);
    int stride = gridDim.x * blockDim.x;
    for (int idx = i; idx < n4_big; idx += stride) {
        ((float4*)g_neigh)[idx] = z;
        ((float4*)g_conv)[idx]  = z;
        if (idx < n4_cnt) ((float4*)g_cnt)[idx] = z;
    }
}

// ---------------- in-degree count ----------------
__global__ void count_k(const int* __restrict__ dst, int E, int N) {
    int i = blockIdx.x * blockDim.x + threadIdx.x;
    if (i < E) {
        int d = dst[i];
        d = min(max(d, 0), N - 1);   // safety clamp (no-op for valid data)
        atomicAdd(&g_cnt[d], 1);
    }
}

__global__ void inv_k(int N) {
    int i = blockIdx.x * blockDim.x + threadIdx.x;
    if (i < N) g_inv[i] = 1.0f / fmaxf((float)g_cnt[i], 1.0f);
}

// ---------------- generic C = [A0 | A1*rs] @ [W0;W1] + bias ----------------
// A0,A1: N x 128 row-major.  W0,W1: 128 x 128 row-major.  C: N x 128.
// rs (nullable): per-row scale applied to the A1 half.
__global__ __launch_bounds__(256)
void gemm_k(const float* __restrict__ A0, const float* __restrict__ A1,
            const float* __restrict__ rs,
            const float* __restrict__ W0, const float* __restrict__ W1,
            const float* __restrict__ bias,
            float* __restrict__ C, int N)
{
    __shared__ float As[16][128];
    __shared__ float Bs[16][128];
    int tid = threadIdx.x;
    int blockRow = blockIdx.x * 128;
    int tx = tid & 15, ty = tid >> 4;

    float acc[8][8];
    #pragma unroll
    for (int i = 0; i < 8; i++)
        #pragma unroll
        for (int j = 0; j < 8; j++) acc[i][j] = 0.f;

    int rowA = tid >> 2;          // 0..63  (+64 for second)
    int ka   = (tid & 3) * 4;     // 0,4,8,12
    int rowB = tid >> 5;          // 0..7   (+8)
    int colB = (tid & 31) * 4;    // 0..124

    for (int k0 = 0; k0 < 256; k0 += 16) {
        #pragma unroll
        for (int rr = 0; rr < 2; rr++) {
            int r = rowA + rr * 64;
            int grow = blockRow + r;
            float4 v = make_float4(0.f, 0.f, 0.f, 0.f);
            int ksrc = k0 + ka;
            if (grow < N) {
                const float* Aptr = (ksrc < 128) ? (A0 + (size_t)grow * 128 + ksrc)
                                                 : (A1 + (size_t)grow * 128 + (ksrc - 128));
                v = *(const float4*)Aptr;
                if (ksrc >= 128 && rs) {
                    float s = rs[grow];
                    v.x *= s; v.y *= s; v.z *= s; v.w *= s;
                }
            }
            As[ka + 0][r] = v.x; As[ka + 1][r] = v.y;
            As[ka + 2][r] = v.z; As[ka + 3][r] = v.w;
        }
        #pragma unroll
        for (int rr = 0; rr < 2; rr++) {
            int kk = rowB + rr * 8;
            int ksrc = k0 + kk;
            const float* Wptr = (ksrc < 128) ? (W0 + ksrc * 128 + colB)
                                             : (W1 + (ksrc - 128) * 128 + colB);
            *(float4*)&Bs[kk][colB] = *(const float4*)Wptr;
        }
        __syncthreads();

        #pragma unroll
        for (int k = 0; k < 16; k++) {
            float a[8], b[8];
            #pragma unroll
            for (int i = 0; i < 8; i++) a[i] = As[k][ty * 8 + i];
            #pragma unroll
            for (int j = 0; j < 8; j++) b[j] = Bs[k][tx * 8 + j];
            #pragma unroll
            for (int i = 0; i < 8; i++)
                #pragma unroll
                for (int j = 0; j < 8; j++)
                    acc[i][j] += a[i] * b[j];
        }
        __syncthreads();
    }

    #pragma unroll
    for (int i = 0; i < 8; i++) {
        int grow = blockRow + ty * 8 + i;
        if (grow < N) {
            #pragma unroll
            for (int j = 0; j < 8; j += 4) {
                int col = tx * 8 + j;
                float4 v;
                v.x = acc[i][j + 0] + bias[col + 0];
                v.y = acc[i][j + 1] + bias[col + 1];
                v.z = acc[i][j + 2] + bias[col + 2];
                v.w = acc[i][j + 3] + bias[col + 3];
                *(float4*)&C[(size_t)grow * 128 + col] = v;
            }
        }
    }
}

// ---------------- LayerNorm + ReLU (warp per row) ----------------
__global__ void ln_relu_k(const float* __restrict__ E_,
                          const float* __restrict__ gma,
                          const float* __restrict__ bta,
                          float* __restrict__ M, int N)
{
    int warp = (blockIdx.x * blockDim.x + threadIdx.x) >> 5;
    int lane = threadIdx.x & 31;
    if (warp >= N) return;
    float4 v = *(const float4*)&E_[(size_t)warp * 128 + lane * 4];
    float s  = v.x + v.y + v.z + v.w;
    float sq = v.x * v.x + v.y * v.y + v.z * v.z + v.w * v.w;
    #pragma unroll
    for (int o = 16; o; o >>= 1) {
        s  += __shfl_xor_sync(0xffffffffu, s,  o);
        sq += __shfl_xor_sync(0xffffffffu, sq, o);
    }
    float mu  = s * (1.f / 128.f);
    float var = sq * (1.f / 128.f) - mu * mu;
    float r   = rsqrtf(var + 1e-5f);
    float4 gv = *(const float4*)&gma[lane * 4];
    float4 bv = *(const float4*)&bta[lane * 4];
    float4 o;
    o.x = fmaxf((v.x - mu) * r * gv.x + bv.x, 0.f);
    o.y = fmaxf((v.y - mu) * r * gv.y + bv.y, 0.f);
    o.z = fmaxf((v.z - mu) * r * gv.z + bv.z, 0.f);
    o.w = fmaxf((v.w - mu) * r * gv.w + bv.w, 0.f);
    *(float4*)&M[(size_t)warp * 128 + lane * 4] = o;
}

// ---------------- edge scatter: neigh_sum += h[src], conv_sum += m[src] ----------------
__global__ void scatter_k(const float* __restrict__ h,
                          const int* __restrict__ src, const int* __restrict__ dst,
                          int E, int N)
{
    int e = (blockIdx.x * blockDim.x + threadIdx.x) >> 5;
    int lane = threadIdx.x & 31;
    if (e >= E) return;
    int s = src[e], d = dst[e];
    s = min(max(s, 0), N - 1);   // safety clamps (no-op for valid data)
    d = min(max(d, 0), N - 1);
    size_t so = (size_t)s * 128 + lane * 4;
    size_t doff = (size_t)d * 128 + lane * 4;
    float4 vh = *(const float4*)&h[so];
    float4 vm = *(const float4*)&g_m[so];
    red_add_v4(&g_neigh[doff], vh);
    red_add_v4(&g_conv[doff],  vm);
}

// ---------------- gated fusion epilogue ----------------
__global__ void final_k(float* __restrict__ out, int N)
{
    int i4 = blockIdx.x * blockDim.x + threadIdx.x;
    if (i4 >= N * 32) return;
    int row = i4 >> 5;
    float s = g_inv[row];
    float4 gv = ((const float4*)g_tmp)[i4];
    float4 sv = ((const float4*)g_std)[i4];
    float4 cv = ((const float4*)g_conv)[i4];
    cv.x *= s; cv.y *= s; cv.z *= s; cv.w *= s;
    float4 o;
    float t;
    t = 1.f / (1.f + expf(-gv.x)); o.x = t * sv.x + (1.f - t) * cv.x;
    t = 1.f / (1.f + expf(-gv.y)); o.y = t * sv.y + (1.f - t) * cv.y;
    t = 1.f / (1.f + expf(-gv.z)); o.z = t * sv.z + (1.f - t) * cv.z;
    t = 1.f / (1.f + expf(-gv.w)); o.w = t * sv.w + (1.f - t) * cv.w;
    ((float4*)out)[i4] = o;
}

// ---------------- launch ----------------
extern "C" void kernel_launch(void* const* d_in, const int* in_sizes, int n_in,
                              void* d_out, int out_size)
{
    // metadata.txt order == setup_inputs() dict order
    const float* h      = (const float*)d_in[0];
    const float* ctx    = (const float*)d_in[1];
    const int*   src    = (const int*)  d_in[2];
    const int*   dst    = (const int*)  d_in[3];
    const float* W_self = (const float*)d_in[4];
    const float* W_neigh= (const float*)d_in[5];
    const float* b_sage = (const float*)d_in[6];
    const float* Wm     = (const float*)d_in[7];
    const float* bm     = (const float*)d_in[8];
    const float* ln_g   = (const float*)d_in[9];
    const float* ln_b   = (const float*)d_in[10];
    const float* Wg     = (const float*)d_in[11];
    const float* bg     = (const float*)d_in[12];
    float* out = (float*)d_out;

    int N = in_sizes[0] / 128;
    if (N < 1) N = 1;
    if (N > MAXN) N = MAXN;
    int E = in_sizes[2];

    // CRITICAL (GB300/ATS pitfall): __device__ symbols must be resolved to
    // device addresses before being passed as kernel arguments from host code.
    // Passing the symbol directly gives the HOST shadow address, which ATS
    // happily dereferences into host memory — silently wrong results.
    float *p_neigh = nullptr, *p_conv = nullptr, *p_m = nullptr;
    float *p_std = nullptr, *p_tmp = nullptr, *p_inv = nullptr;
    cudaGetSymbolAddress((void**)&p_neigh, g_neigh);
    cudaGetSymbolAddress((void**)&p_conv,  g_conv);
    cudaGetSymbolAddress((void**)&p_m,     g_m);
    cudaGetSymbolAddress((void**)&p_std,   g_std);
    cudaGetSymbolAddress((void**)&p_tmp,   g_tmp);
    cudaGetSymbolAddress((void**)&p_inv,   g_inv);

    int n4_big = MAXN * 32;            // float4 count per [MAXN*128] array
    int n4_cnt = MAXN / 4;

    // 1) zero accumulators
    zero_k<<<1024, 256>>>(n4_big, n4_cnt);
    // 2) in-degree counts
    count_k<<<(E + 255) / 256, 256>>>(dst, E, N);
    // 3) inverse safe counts
    inv_k<<<(N + 255) / 256, 256>>>(N);
    // 4) e = [h|ctx] @ Wm + bm
    int gblocks = (N + 127) / 128;
    gemm_k<<<gblocks, 256>>>(h, ctx, nullptr, Wm, Wm + 128 * 128, bm, p_tmp, N);
    // 5) m = relu(LN(e))
    ln_relu_k<<<(N * 32 + 255) / 256, 256>>>(p_tmp, ln_g, ln_b, p_m, N);
    // 6) scatter h[src] and m[src] into per-dst sums
    scatter_k<<<(E * 32 + 255) / 256, 256>>>(h, src, dst, E, N);
    // 7) standard = h @ W_self + (neigh_sum*inv) @ W_neigh + b_sage
    gemm_k<<<gblocks, 256>>>(h, p_neigh, p_inv, W_self, W_neigh, b_sage, p_std, N);
    // 8) G = [standard | conv_sum*inv] @ Wg + bg
    gemm_k<<<gblocks, 256>>>(p_std, p_conv, p_inv, Wg, Wg + 128 * 128, bg, p_tmp, N);
    // 9) out = sig(G)*standard + (1-sig(G))*conv_agg
    final_k<<<(N * 32 + 255) / 256, 256>>>(out, N);
}

// round 10
// speedup vs baseline: 1.4069x; 1.4069x over previous
#include <cuda_runtime.h>
#include <cuda_bf16.h>
#include <cstdint>

#define DD 128
#define MAXN 50176            // >= N, multiple of 128
#define MAXTILES (MAXN / 128) // 392

// ---------------- scratch (static __device__; allocation-free) ----------------
__device__ __align__(128) int   g_cnt[MAXN];
__device__ __align__(128) float g_inv[MAXN];
__device__ __align__(128) float g_neigh[MAXN * DD];
__device__ __align__(128) float g_conv [MAXN * DD];
__device__ __align__(128) float g_m    [MAXN * DD];
__device__ __align__(128) float g_std  [MAXN * DD];
// bf16 split operand buffers, ROW-MAJOR [rows x 256]
__device__ __align__(128) __nv_bfloat16 g_A0hi[MAXN * 256];
__device__ __align__(128) __nv_bfloat16 g_A0lo[MAXN * 256];
__device__ __align__(128) __nv_bfloat16 g_A2hi[MAXN * 256];
__device__ __align__(128) __nv_bfloat16 g_A2lo[MAXN * 256];
// weight tiles: Bt row-major [128 n x 256 k], 3 gemms x hi/lo
__device__ __align__(128) __nv_bfloat16 g_Bhi[3][128 * 256];
__device__ __align__(128) __nv_bfloat16 g_Blo[3][128 * 256];

// ---------------- helpers ----------------
__device__ __forceinline__ void red_add_v4(float* p, float4 v) {
    asm volatile("red.global.add.v4.f32 [%0], {%1,%2,%3,%4};"
                 :: "l"(p), "f"(v.x), "f"(v.y), "f"(v.z), "f"(v.w) : "memory");
}
__device__ __forceinline__ void split_bf16(float f, __nv_bfloat16& h, __nv_bfloat16& l) {
    h = __float2bfloat16(f);
    l = __float2bfloat16(f - __bfloat162float(h));
}
__device__ __forceinline__ void mma_bf16(float* d, const uint32_t* a, uint32_t b0, uint32_t b1) {
    asm volatile("mma.sync.aligned.m16n8k16.row.col.f32.bf16.bf16.f32 "
                 "{%0,%1,%2,%3}, {%4,%5,%6,%7}, {%8,%9}, {%0,%1,%2,%3};"
                 : "+f"(d[0]), "+f"(d[1]), "+f"(d[2]), "+f"(d[3])
                 : "r"(a[0]), "r"(a[1]), "r"(a[2]), "r"(a[3]), "r"(b0), "r"(b1));
}

// ================= small kernels =================
__global__ void zero_k(int n4_big, int n4_cnt) {
    int i = blockIdx.x * blockDim.x + threadIdx.x;
    float4 z = make_float4(0.f, 0.f, 0.f, 0.f);
    int stride = gridDim.x * blockDim.x;
    for (int idx = i; idx < n4_big; idx += stride) {
        ((float4*)g_neigh)[idx] = z;
        ((float4*)g_conv)[idx]  = z;
        if (idx < n4_cnt) ((float4*)g_cnt)[idx] = z;
    }
}
__global__ void count_k(const int* __restrict__ dst, int E, int N) {
    int i = blockIdx.x * blockDim.x + threadIdx.x;
    if (i < E) {
        int d = dst[i];
        d = min(max(d, 0), N - 1);
        atomicAdd(&g_cnt[d], 1);
    }
}
__global__ void inv_k(int N) {
    int i = blockIdx.x * blockDim.x + threadIdx.x;
    if (i < N) g_inv[i] = 1.0f / fmaxf((float)g_cnt[i], 1.0f);
}

// weights -> transposed + split, row-major Bt[n][k]: B[n][k] = (k<128 ? W0[k][n] : W1[k-128][n])
__global__ void convW_k(const float* __restrict__ W0, const float* __restrict__ W1,
                        __nv_bfloat16* __restrict__ Bh, __nv_bfloat16* __restrict__ Bl) {
    int i = blockIdx.x * blockDim.x + threadIdx.x;
    if (i >= 128 * 256) return;
    int n = i >> 8, k = i & 255;
    float w = (k < 128) ? W0[k * 128 + n] : W1[(k - 128) * 128 + n];
    __nv_bfloat16 hh, ll; split_bf16(w, hh, ll);
    Bh[n * 256 + k] = hh;
    Bl[n * 256 + k] = ll;
}

// activation half -> split, row-major [row*256 + c0 + c]; optional per-row scale
__global__ void convA_k(const float* __restrict__ S, const float* __restrict__ inv,
                        __nv_bfloat16* __restrict__ Ah, __nv_bfloat16* __restrict__ Al,
                        int c0, int N, int rowsTot) {
    int i = blockIdx.x * blockDim.x + threadIdx.x;   // rowsTot * 64 col-pairs
    if (i >= rowsTot * 64) return;
    int r = i >> 6;
    int cp = (i & 63) * 2;
    float2 v = make_float2(0.f, 0.f);
    if (r < N) {
        v = *(const float2*)&S[(size_t)r * 128 + cp];
        if (inv) { float s = inv[r]; v.x *= s; v.y *= s; }
    }
    __nv_bfloat16 h0, l0, h1, l1;
    split_bf16(v.x, h0, l0);
    split_bf16(v.y, h1, l1);
    size_t off = (size_t)r * 256 + c0 + cp;
    __nv_bfloat162 hh; hh.x = h0; hh.y = h1;
    __nv_bfloat162 ll; ll.x = l0; ll.y = l1;
    *(__nv_bfloat162*)&Ah[off] = hh;
    *(__nv_bfloat162*)&Al[off] = ll;
}

// edge scatter
__global__ void scatter_k(const float* __restrict__ h,
                          const int* __restrict__ src, const int* __restrict__ dst,
                          int E, int N) {
    int e = (blockIdx.x * blockDim.x + threadIdx.x) >> 5;
    int lane = threadIdx.x & 31;
    if (e >= E) return;
    int s = src[e], d = dst[e];
    s = min(max(s, 0), N - 1);
    d = min(max(d, 0), N - 1);
    size_t so = (size_t)s * 128 + lane * 4;
    size_t doff = (size_t)d * 128 + lane * 4;
    float4 vh = *(const float4*)&h[so];
    float4 vm = *(const float4*)&g_m[so];
    red_add_v4(&g_neigh[doff], vh);
    red_add_v4(&g_conv[doff],  vm);
}

// ================= HMMA GEMM: D[128x128] = A[128x256] @ Bt^T, 3-pass bf16 split =======
// smem: during mainloop 4 operand tiles [128][40] bf16 (10240 B each);
//       after mainloop reused as C staging float[128][132].
#define SPAD 40                         // bf16 per smem row (32 data + 8 pad)
#define SROWB (SPAD * 2)                // 80 bytes
#define SA_H 0
#define SA_L 10240
#define SB_H 20480
#define SB_L 30720
#define CPAD 132
#define SM_TOTAL (128 * CPAD * 4)       // 67584 bytes

// MODE 0: O0 = relu(LN(D + bias)) with ln_g/ln_b
// MODE 1: O0 = D + bias; split(O0) -> A2 cols [0,128); zero-fill A2 rows [N,rowsTot)
// MODE 2: out = sig(D+bias)*std_in + (1-sig)*conv_in*inv
template<int MODE>
__global__ __launch_bounds__(256)
void mma_k(const __nv_bfloat16* __restrict__ Ahi, const __nv_bfloat16* __restrict__ Alo,
           const __nv_bfloat16* __restrict__ Bhi, const __nv_bfloat16* __restrict__ Blo,
           const float* __restrict__ bias,
           const float* __restrict__ ln_g, const float* __restrict__ ln_b,
           float* __restrict__ O0,
           __nv_bfloat16* __restrict__ A2hi, __nv_bfloat16* __restrict__ A2lo,
           const float* __restrict__ std_in, const float* __restrict__ conv_in,
           const float* __restrict__ inv, int N, int rowsTot)
{
    extern __shared__ __align__(16) char smem[];
    int tid = threadIdx.x;
    int lane = tid & 31, wid = tid >> 5;
    int wm = wid & 3, wn = wid >> 2;          // warp grid 4 (rows) x 2 (cols)
    int gid = lane >> 2;                      // 0..7
    int qid = lane & 3;                       // 0..3
    int tile = blockIdx.x;

    const __nv_bfloat16* gAh = Ahi + (size_t)tile * 128 * 256;
    const __nv_bfloat16* gAl = Alo + (size_t)tile * 128 * 256;

    float acc[2][8][4];
    #pragma unroll
    for (int mt = 0; mt < 2; mt++)
        #pragma unroll
        for (int nt = 0; nt < 8; nt++)
            #pragma unroll
            for (int q = 0; q < 4; q++) acc[mt][nt][q] = 0.f;

    for (int ch = 0; ch < 8; ch++) {
        int k0 = ch * 32;
        __syncthreads();
        // stage 4 operand tiles: each thread copies 2 float4 per matrix
        #pragma unroll
        for (int j = 0; j < 2; j++) {
            int idx = tid + j * 256;          // 0..511
            int row = idx >> 2, c4 = idx & 3;
            size_t goff = (size_t)row * 256 + k0 + c4 * 8;
            uint32_t soff = row * SROWB + c4 * 16;
            *(float4*)(smem + SA_H + soff) = *(const float4*)(gAh + goff);
            *(float4*)(smem + SA_L + soff) = *(const float4*)(gAl + goff);
            *(float4*)(smem + SB_H + soff) = *(const float4*)(Bhi + goff);
            *(float4*)(smem + SB_L + soff) = *(const float4*)(Blo + goff);
        }
        __syncthreads();

        #pragma unroll
        for (int kk = 0; kk < 32; kk += 16) {
            int kc = kk + qid * 2;
            uint32_t ah[2][4], al[2][4];
            #pragma unroll
            for (int mt = 0; mt < 2; mt++) {
                int r0 = wm * 32 + mt * 16 + gid;
                ah[mt][0] = *(const uint32_t*)(smem + SA_H + (r0    ) * SROWB + kc * 2);
                ah[mt][1] = *(const uint32_t*)(smem + SA_H + (r0 + 8) * SROWB + kc * 2);
                ah[mt][2] = *(const uint32_t*)(smem + SA_H + (r0    ) * SROWB + (kc + 8) * 2);
                ah[mt][3] = *(const uint32_t*)(smem + SA_H + (r0 + 8) * SROWB + (kc + 8) * 2);
                al[mt][0] = *(const uint32_t*)(smem + SA_L + (r0    ) * SROWB + kc * 2);
                al[mt][1] = *(const uint32_t*)(smem + SA_L + (r0 + 8) * SROWB + kc * 2);
                al[mt][2] = *(const uint32_t*)(smem + SA_L + (r0    ) * SROWB + (kc + 8) * 2);
                al[mt][3] = *(const uint32_t*)(smem + SA_L + (r0 + 8) * SROWB + (kc + 8) * 2);
            }
            #pragma unroll
            for (int nt = 0; nt < 8; nt++) {
                int n0 = wn * 64 + nt * 8 + gid;
                uint32_t bh0 = *(const uint32_t*)(smem + SB_H + n0 * SROWB + kc * 2);
                uint32_t bh1 = *(const uint32_t*)(smem + SB_H + n0 * SROWB + (kc + 8) * 2);
                uint32_t bl0 = *(const uint32_t*)(smem + SB_L + n0 * SROWB + kc * 2);
                uint32_t bl1 = *(const uint32_t*)(smem + SB_L + n0 * SROWB + (kc + 8) * 2);
                #pragma unroll
                for (int mt = 0; mt < 2; mt++) {
                    mma_bf16(acc[mt][nt], ah[mt], bh0, bh1);   // Ah*Bh
                    mma_bf16(acc[mt][nt], al[mt], bh0, bh1);   // Al*Bh
                    mma_bf16(acc[mt][nt], ah[mt], bl0, bl1);   // Ah*Bl
                }
            }
        }
    }

    // ---- stage C to smem (reuse operand region) ----
    __syncthreads();
    float* Cs = (float*)smem;
    #pragma unroll
    for (int mt = 0; mt < 2; mt++) {
        #pragma unroll
        for (int nt = 0; nt < 8; nt++) {
            int r0 = wm * 32 + mt * 16 + gid;
            int c0 = wn * 64 + nt * 8 + qid * 2;
            Cs[(r0    ) * CPAD + c0    ] = acc[mt][nt][0];
            Cs[(r0    ) * CPAD + c0 + 1] = acc[mt][nt][1];
            Cs[(r0 + 8) * CPAD + c0    ] = acc[mt][nt][2];
            Cs[(r0 + 8) * CPAD + c0 + 1] = acc[mt][nt][3];
        }
    }
    __syncthreads();

    // ---- epilogue: warp handles 16 rows ----
    for (int rr = wid * 16; rr < wid * 16 + 16; rr++) {
        int row = tile * 128 + rr;
        int c = lane * 4;
        if (MODE == 1 && row >= N && row < rowsTot) {
            // zero-fill A2 first half for padded rows
            __nv_bfloat162 z; z.x = __float2bfloat16(0.f); z.y = z.x;
            size_t off = (size_t)row * 256 + c;
            *(__nv_bfloat162*)&A2hi[off] = z; *(__nv_bfloat162*)&A2hi[off + 2] = z;
            *(__nv_bfloat162*)&A2lo[off] = z; *(__nv_bfloat162*)&A2lo[off + 2] = z;
            continue;
        }
        if (row >= N) continue;
        float4 v = *(const float4*)&Cs[rr * CPAD + c];
        float4 bv = *(const float4*)&bias[c];
        v.x += bv.x; v.y += bv.y; v.z += bv.z; v.w += bv.w;

        if (MODE == 0) {
            float s = v.x + v.y + v.z + v.w;
            float sq = v.x * v.x + v.y * v.y + v.z * v.z + v.w * v.w;
            #pragma unroll
            for (int o = 16; o; o >>= 1) {
                s  += __shfl_xor_sync(0xffffffffu, s,  o);
                sq += __shfl_xor_sync(0xffffffffu, sq, o);
            }
            float mu = s * (1.f / 128.f);
            float var = sq * (1.f / 128.f) - mu * mu;
            float r = rsqrtf(var + 1e-5f);
            float4 gv = *(const float4*)&ln_g[c];
            float4 lb = *(const float4*)&ln_b[c];
            float4 o;
            o.x = fmaxf((v.x - mu) * r * gv.x + lb.x, 0.f);
            o.y = fmaxf((v.y - mu) * r * gv.y + lb.y, 0.f);
            o.z = fmaxf((v.z - mu) * r * gv.z + lb.z, 0.f);
            o.w = fmaxf((v.w - mu) * r * gv.w + lb.w, 0.f);
            *(float4*)&O0[(size_t)row * 128 + c] = o;
        } else if (MODE == 1) {
            *(float4*)&O0[(size_t)row * 128 + c] = v;
            __nv_bfloat16 h0, l0, h1, l1, h2, l2, h3, l3;
            split_bf16(v.x, h0, l0); split_bf16(v.y, h1, l1);
            split_bf16(v.z, h2, l2); split_bf16(v.w, h3, l3);
            size_t off = (size_t)row * 256 + c;
            __nv_bfloat162 hh0; hh0.x = h0; hh0.y = h1;
            __nv_bfloat162 hh1; hh1.x = h2; hh1.y = h3;
            __nv_bfloat162 ll0; ll0.x = l0; ll0.y = l1;
            __nv_bfloat162 ll1; ll1.x = l2; ll1.y = l3;
            *(__nv_bfloat162*)&A2hi[off] = hh0; *(__nv_bfloat162*)&A2hi[off + 2] = hh1;
            *(__nv_bfloat162*)&A2lo[off] = ll0; *(__nv_bfloat162*)&A2lo[off + 2] = ll1;
        } else {
            float iv = inv[row];
            float4 sv = *(const float4*)&std_in[(size_t)row * 128 + c];
            float4 cv = *(const float4*)&conv_in[(size_t)row * 128 + c];
            float4 o; float g;
            g = 1.f / (1.f + expf(-v.x)); o.x = g * sv.x + (1.f - g) * cv.x * iv;
            g = 1.f / (1.f + expf(-v.y)); o.y = g * sv.y + (1.f - g) * cv.y * iv;
            g = 1.f / (1.f + expf(-v.z)); o.z = g * sv.z + (1.f - g) * cv.z * iv;
            g = 1.f / (1.f + expf(-v.w)); o.w = g * sv.w + (1.f - g) * cv.w * iv;
            *(float4*)&O0[(size_t)row * 128 + c] = o;
        }
    }
}

// ================= launch =================
extern "C" void kernel_launch(void* const* d_in, const int* in_sizes, int n_in,
                              void* d_out, int out_size)
{
    const float* h      = (const float*)d_in[0];
    const float* ctx    = (const float*)d_in[1];
    const int*   src    = (const int*)  d_in[2];
    const int*   dst    = (const int*)  d_in[3];
    const float* W_self = (const float*)d_in[4];
    const float* W_neigh= (const float*)d_in[5];
    const float* b_sage = (const float*)d_in[6];
    const float* Wm     = (const float*)d_in[7];
    const float* bm     = (const float*)d_in[8];
    const float* ln_g   = (const float*)d_in[9];
    const float* ln_b   = (const float*)d_in[10];
    const float* Wg     = (const float*)d_in[11];
    const float* bg     = (const float*)d_in[12];
    float* out = (float*)d_out;

    int N = in_sizes[0] / 128;
    if (N < 1) N = 1;
    if (N > MAXN) N = MAXN;
    int E = in_sizes[2];
    int tiles = (N + 127) / 128;
    int rowsTot = tiles * 128;

    // resolve device addresses of __device__ symbols (GB300/ATS pitfall)
    float *p_neigh, *p_conv, *p_m, *p_std, *p_inv;
    __nv_bfloat16 *pA0h, *pA0l, *pA2h, *pA2l, *pBh, *pBl;
    cudaGetSymbolAddress((void**)&p_neigh, g_neigh);
    cudaGetSymbolAddress((void**)&p_conv,  g_conv);
    cudaGetSymbolAddress((void**)&p_m,     g_m);
    cudaGetSymbolAddress((void**)&p_std,   g_std);
    cudaGetSymbolAddress((void**)&p_inv,   g_inv);
    cudaGetSymbolAddress((void**)&pA0h,    g_A0hi);
    cudaGetSymbolAddress((void**)&pA0l,    g_A0lo);
    cudaGetSymbolAddress((void**)&pA2h,    g_A2hi);
    cudaGetSymbolAddress((void**)&pA2l,    g_A2lo);
    cudaGetSymbolAddress((void**)&pBh,     g_Bhi);
    cudaGetSymbolAddress((void**)&pBl,     g_Blo);

    cudaFuncSetAttribute(mma_k<0>, cudaFuncAttributeMaxDynamicSharedMemorySize, SM_TOTAL);
    cudaFuncSetAttribute(mma_k<1>, cudaFuncAttributeMaxDynamicSharedMemorySize, SM_TOTAL);
    cudaFuncSetAttribute(mma_k<2>, cudaFuncAttributeMaxDynamicSharedMemorySize, SM_TOTAL);

    int n4_big = MAXN * 32, n4_cnt = MAXN / 4;
    int pthreads = rowsTot * 64;

    // 1) zero accumulators
    zero_k<<<1024, 256>>>(n4_big, n4_cnt);
    // 2-3) degree + inverse
    count_k<<<(E + 255) / 256, 256>>>(dst, E, N);
    inv_k<<<(N + 255) / 256, 256>>>(N);
    // 4) weights -> split: [Wm], [W_self;W_neigh], [Wg]
    convW_k<<<(128 * 256 + 255) / 256, 256>>>(Wm,     Wm + 128 * 128, pBh + 0 * 32768, pBl + 0 * 32768);
    convW_k<<<(128 * 256 + 255) / 256, 256>>>(W_self, W_neigh,        pBh + 1 * 32768, pBl + 1 * 32768);
    convW_k<<<(128 * 256 + 255) / 256, 256>>>(Wg,     Wg + 128 * 128, pBh + 2 * 32768, pBl + 2 * 32768);
    // 5) A0 = [h | ctx] split
    convA_k<<<(pthreads + 255) / 256, 256>>>(h,   nullptr, pA0h, pA0l, 0,   N, rowsTot);
    convA_k<<<(pthreads + 255) / 256, 256>>>(ctx, nullptr, pA0h, pA0l, 128, N, rowsTot);
    // 6) GEMM0 + fused LN/ReLU -> g_m
    mma_k<0><<<tiles, 256, SM_TOTAL>>>(pA0h, pA0l, pBh, pBl, bm, ln_g, ln_b,
                                       p_m, nullptr, nullptr, nullptr, nullptr, p_inv, N, rowsTot);
    // 7) scatter h[src], m[src] -> per-dst sums
    scatter_k<<<((size_t)E * 32 + 255) / 256, 256>>>(h, src, dst, E, N);
    // 8) A0 second half <- neigh_mean split
    convA_k<<<(pthreads + 255) / 256, 256>>>(p_neigh, p_inv, pA0h, pA0l, 128, N, rowsTot);
    // 9) A2 second half <- conv_mean split
    convA_k<<<(pthreads + 255) / 256, 256>>>(p_conv, p_inv, pA2h, pA2l, 128, N, rowsTot);
    // 10) GEMM1 -> g_std, and split(std) into A2 first half
    mma_k<1><<<tiles, 256, SM_TOTAL>>>(pA0h, pA0l, pBh + 1 * 32768, pBl + 1 * 32768, b_sage,
                                       nullptr, nullptr, p_std, pA2h, pA2l, nullptr, nullptr, p_inv, N, rowsTot);
    // 11) GEMM2 + fused sigmoid/blend -> out
    mma_k<2><<<tiles, 256, SM_TOTAL>>>(pA2h, pA2l, pBh + 2 * 32768, pBl + 2 * 32768, bg,
                                       nullptr, nullptr, out, nullptr, nullptr, p_std, p_conv, p_inv, N, rowsTot);
}

// round 11
// speedup vs baseline: 2.5305x; 1.7986x over previous
#include <cuda_runtime.h>
#include <cuda_bf16.h>
#include <cstdint>

#define DD 128
#define MAXN 50176            // >= N, multiple of 256*196
#define MAXTILES (MAXN / 128) // 392
#define MAXE (1 << 20)

// ---------------- scratch (static __device__; allocation-free) ----------------
__device__ __align__(128) int   g_cnt[MAXN];
__device__ __align__(128) int   g_cur[MAXN];
__device__ __align__(128) int   g_off[MAXN + 1];
__device__ __align__(128) int   g_bsum[256];
__device__ __align__(128) int   g_bpre[256];
__device__            int   g_total;
__device__ __align__(128) int   g_csr[MAXE];
__device__ __align__(128) float g_conv [MAXN * DD];   // conv_agg (mean-scaled)
__device__ __align__(128) float g_m    [MAXN * DD];
__device__ __align__(128) float g_std  [MAXN * DD];
// bf16 split operand buffers, ROW-MAJOR [rows x 256]
__device__ __align__(128) __nv_bfloat16 g_A0hi[MAXN * 256];
__device__ __align__(128) __nv_bfloat16 g_A0lo[MAXN * 256];
__device__ __align__(128) __nv_bfloat16 g_A2hi[MAXN * 256];
__device__ __align__(128) __nv_bfloat16 g_A2lo[MAXN * 256];
// weight tiles: Bt row-major [128 n x 256 k], 3 gemms x hi/lo
__device__ __align__(128) __nv_bfloat16 g_Bhi[3][128 * 256];
__device__ __align__(128) __nv_bfloat16 g_Blo[3][128 * 256];

// ---------------- helpers ----------------
__device__ __forceinline__ void split_bf16(float f, __nv_bfloat16& h, __nv_bfloat16& l) {
    h = __float2bfloat16(f);
    l = __float2bfloat16(f - __bfloat162float(h));
}
__device__ __forceinline__ void mma_bf16(float* d, const uint32_t* a, uint32_t b0, uint32_t b1) {
    asm volatile("mma.sync.aligned.m16n8k16.row.col.f32.bf16.bf16.f32 "
                 "{%0,%1,%2,%3}, {%4,%5,%6,%7}, {%8,%9}, {%0,%1,%2,%3};"
                 : "+f"(d[0]), "+f"(d[1]), "+f"(d[2]), "+f"(d[3])
                 : "r"(a[0]), "r"(a[1]), "r"(a[2]), "r"(a[3]), "r"(b0), "r"(b1));
}

// ================= CSR build =================
__global__ void zero_small_k() {
    int i = blockIdx.x * blockDim.x + threadIdx.x;
    if (i < MAXN) { g_cnt[i] = 0; g_cur[i] = 0; }
}
__global__ void count_k(const int* __restrict__ dst, int E, int N) {
    int i = blockIdx.x * blockDim.x + threadIdx.x;
    if (i < E) {
        int d = dst[i];
        d = min(max(d, 0), N - 1);
        atomicAdd(&g_cnt[d], 1);
    }
}
// exclusive scan of g_cnt[MAXN] -> g_off, 3 stages (MAXN = 196*256)
__global__ void scan1_k() {
    __shared__ int sm[256];
    int b = blockIdx.x, t = threadIdx.x;
    int v = g_cnt[b * 256 + t];
    sm[t] = v;
    __syncthreads();
    int acc = v;
    #pragma unroll
    for (int o = 1; o < 256; o <<= 1) {
        int p = (t >= o) ? sm[t - o] : 0;
        __syncthreads();
        acc += p; sm[t] = acc;
        __syncthreads();
    }
    g_off[b * 256 + t] = acc - v;              // block-local exclusive
    if (t == 255) g_bsum[b] = acc;
}
__global__ void scan2_k(int nb) {
    __shared__ int sm[256];
    int t = threadIdx.x;
    int v = (t < nb) ? g_bsum[t] : 0;
    sm[t] = v;
    __syncthreads();
    int acc = v;
    #pragma unroll
    for (int o = 1; o < 256; o <<= 1) {
        int p = (t >= o) ? sm[t - o] : 0;
        __syncthreads();
        acc += p; sm[t] = acc;
        __syncthreads();
    }
    g_bpre[t] = acc - v;                        // exclusive block prefix
    if (t == 255) g_total = acc;
}
__global__ void scan3_k() {
    int i = blockIdx.x * blockDim.x + threadIdx.x;
    if (i < MAXN) g_off[i] += g_bpre[i >> 8];
    if (i == 0) g_off[MAXN] = g_total;
}
__global__ void fill_k(const int* __restrict__ src, const int* __restrict__ dst, int E, int N) {
    int i = blockIdx.x * blockDim.x + threadIdx.x;
    if (i >= E) return;
    int d = dst[i];
    d = min(max(d, 0), N - 1);
    int pos = g_off[d] + atomicAdd(&g_cur[d], 1);
    if (pos < MAXE) {
        int s = src[i];
        g_csr[pos] = min(max(s, 0), N - 1);
    }
}

// ================= operand conversion =================
// all 3 weight blocks -> transposed + split, row-major Bt[n][k]
__global__ void convW3_k(const float* __restrict__ Wm, const float* __restrict__ W_self,
                         const float* __restrict__ W_neigh, const float* __restrict__ Wg) {
    int i = blockIdx.x * blockDim.x + threadIdx.x;
    if (i >= 3 * 128 * 256) return;
    int g = i >> 15;           // gemm id
    int r = i & 32767;
    int n = r >> 8, k = r & 255;
    float w;
    if (g == 0)      w = Wm[k * 128 + n];                                     // [Wm ; Wm+]
    else if (g == 1) w = (k < 128) ? W_self[k * 128 + n] : W_neigh[(k - 128) * 128 + n];
    else             w = Wg[k * 128 + n];
    __nv_bfloat16 hh, ll; split_bf16(w, hh, ll);
    g_Bhi[g][n * 256 + k] = hh;
    g_Blo[g][n * 256 + k] = ll;
}

// A0 = split([h | ctx]) row-major [rowsTot x 256]
__global__ void convA2_k(const float* __restrict__ h, const float* __restrict__ ctx,
                         __nv_bfloat16* __restrict__ Ah, __nv_bfloat16* __restrict__ Al,
                         int N, int rowsTot) {
    int i = blockIdx.x * blockDim.x + threadIdx.x;   // rowsTot*128 col-pairs
    if (i >= rowsTot * 128) return;
    int r = i >> 7;
    int cp = (i & 127) * 2;                          // 0..254
    float2 v = make_float2(0.f, 0.f);
    if (r < N) {
        const float* S = (cp < 128) ? h : ctx;
        int c = cp & 127;
        v = *(const float2*)&S[(size_t)r * 128 + c];
    }
    __nv_bfloat16 h0, l0, h1, l1;
    split_bf16(v.x, h0, l0);
    split_bf16(v.y, h1, l1);
    size_t off = (size_t)r * 256 + cp;
    __nv_bfloat162 hh; hh.x = h0; hh.y = h1;
    __nv_bfloat162 ll; ll.x = l0; ll.y = l1;
    *(__nv_bfloat162*)&Ah[off] = hh;
    *(__nv_bfloat162*)&Al[off] = ll;
}

// ================= CSR aggregation (atomic-free) =================
// warp per dst node: sums h[src], m[src]; writes
//   A0[d][128:256] = split(neigh_mean), g_conv[d] = conv_agg (fp32, mean),
//   A2[d][128:256] = split(conv_agg)
__global__ void agg_k(const float* __restrict__ h,
                      __nv_bfloat16* __restrict__ A0h, __nv_bfloat16* __restrict__ A0l,
                      __nv_bfloat16* __restrict__ A2h, __nv_bfloat16* __restrict__ A2l,
                      float* __restrict__ conv_out, int rowsTot)
{
    int d = (blockIdx.x * blockDim.x + threadIdx.x) >> 5;
    int lane = threadIdx.x & 31;
    if (d >= rowsTot) return;
    int e0 = g_off[d], e1 = g_off[d + 1];
    int cnt = e1 - e0;
    float4 sh = make_float4(0.f, 0.f, 0.f, 0.f);
    float4 sm = make_float4(0.f, 0.f, 0.f, 0.f);
    for (int e = e0; e < e1; e++) {
        int s = g_csr[e];
        size_t so = (size_t)s * 128 + lane * 4;
        float4 vh = *(const float4*)&h[so];
        float4 vm = *(const float4*)&g_m[so];
        sh.x += vh.x; sh.y += vh.y; sh.z += vh.z; sh.w += vh.w;
        sm.x += vm.x; sm.y += vm.y; sm.z += vm.z; sm.w += vm.w;
    }
    float iv = 1.0f / fmaxf((float)cnt, 1.0f);
    sh.x *= iv; sh.y *= iv; sh.z *= iv; sh.w *= iv;
    sm.x *= iv; sm.y *= iv; sm.z *= iv; sm.w *= iv;

    // conv_agg fp32
    *(float4*)&conv_out[(size_t)d * 128 + lane * 4] = sm;

    // split neigh_mean -> A0 second half; split conv_agg -> A2 second half
    size_t off = (size_t)d * 256 + 128 + lane * 4;
    __nv_bfloat16 a, b;
    __nv_bfloat162 hh0, hh1, ll0, ll1;
    split_bf16(sh.x, a, b); hh0.x = a; ll0.x = b;
    split_bf16(sh.y, a, b); hh0.y = a; ll0.y = b;
    split_bf16(sh.z, a, b); hh1.x = a; ll1.x = b;
    split_bf16(sh.w, a, b); hh1.y = a; ll1.y = b;
    *(__nv_bfloat162*)&A0h[off] = hh0; *(__nv_bfloat162*)&A0h[off + 2] = hh1;
    *(__nv_bfloat162*)&A0l[off] = ll0; *(__nv_bfloat162*)&A0l[off + 2] = ll1;
    split_bf16(sm.x, a, b); hh0.x = a; ll0.x = b;
    split_bf16(sm.y, a, b); hh0.y = a; ll0.y = b;
    split_bf16(sm.z, a, b); hh1.x = a; ll1.x = b;
    split_bf16(sm.w, a, b); hh1.y = a; ll1.y = b;
    *(__nv_bfloat162*)&A2h[off] = hh0; *(__nv_bfloat162*)&A2h[off + 2] = hh1;
    *(__nv_bfloat162*)&A2l[off] = ll0; *(__nv_bfloat162*)&A2l[off + 2] = ll1;
}

// ================= HMMA GEMM: D[128x128] = A[128x256] @ Bt^T, 3-pass bf16 split =======
#define SPAD 40
#define SROWB (SPAD * 2)
#define SA_H 0
#define SA_L 10240
#define SB_H 20480
#define SB_L 30720
#define CPAD 132
#define SM_TOTAL (128 * CPAD * 4)

// MODE 0: O0 = relu(LN(D + bias)) with ln_g/ln_b
// MODE 1: O0 = D + bias; split(O0) -> A2 cols [0,128); zero-fill A2 rows [N,rowsTot)
// MODE 2: out = sig(D+bias)*std_in + (1-sig)*conv_in   (conv_in pre-scaled)
template<int MODE>
__global__ __launch_bounds__(256)
void mma_k(const __nv_bfloat16* __restrict__ Ahi, const __nv_bfloat16* __restrict__ Alo,
           const __nv_bfloat16* __restrict__ Bhi, const __nv_bfloat16* __restrict__ Blo,
           const float* __restrict__ bias,
           const float* __restrict__ ln_g, const float* __restrict__ ln_b,
           float* __restrict__ O0,
           __nv_bfloat16* __restrict__ A2hi, __nv_bfloat16* __restrict__ A2lo,
           const float* __restrict__ std_in, const float* __restrict__ conv_in,
           int N, int rowsTot)
{
    extern __shared__ __align__(16) char smem[];
    int tid = threadIdx.x;
    int lane = tid & 31, wid = tid >> 5;
    int wm = wid & 3, wn = wid >> 2;
    int gid = lane >> 2;
    int qid = lane & 3;
    int tile = blockIdx.x;

    const __nv_bfloat16* gAh = Ahi + (size_t)tile * 128 * 256;
    const __nv_bfloat16* gAl = Alo + (size_t)tile * 128 * 256;

    float acc[2][8][4];
    #pragma unroll
    for (int mt = 0; mt < 2; mt++)
        #pragma unroll
        for (int nt = 0; nt < 8; nt++)
            #pragma unroll
            for (int q = 0; q < 4; q++) acc[mt][nt][q] = 0.f;

    for (int ch = 0; ch < 8; ch++) {
        int k0 = ch * 32;
        __syncthreads();
        #pragma unroll
        for (int j = 0; j < 2; j++) {
            int idx = tid + j * 256;
            int row = idx >> 2, c4 = idx & 3;
            size_t goff = (size_t)row * 256 + k0 + c4 * 8;
            uint32_t soff = row * SROWB + c4 * 16;
            *(float4*)(smem + SA_H + soff) = *(const float4*)(gAh + goff);
            *(float4*)(smem + SA_L + soff) = *(const float4*)(gAl + goff);
            *(float4*)(smem + SB_H + soff) = *(const float4*)(Bhi + goff);
            *(float4*)(smem + SB_L + soff) = *(const float4*)(Blo + goff);
        }
        __syncthreads();

        #pragma unroll
        for (int kk = 0; kk < 32; kk += 16) {
            int kc = kk + qid * 2;
            uint32_t ah[2][4], al[2][4];
            #pragma unroll
            for (int mt = 0; mt < 2; mt++) {
                int r0 = wm * 32 + mt * 16 + gid;
                ah[mt][0] = *(const uint32_t*)(smem + SA_H + (r0    ) * SROWB + kc * 2);
                ah[mt][1] = *(const uint32_t*)(smem + SA_H + (r0 + 8) * SROWB + kc * 2);
                ah[mt][2] = *(const uint32_t*)(smem + SA_H + (r0    ) * SROWB + (kc + 8) * 2);
                ah[mt][3] = *(const uint32_t*)(smem + SA_H + (r0 + 8) * SROWB + (kc + 8) * 2);
                al[mt][0] = *(const uint32_t*)(smem + SA_L + (r0    ) * SROWB + kc * 2);
                al[mt][1] = *(const uint32_t*)(smem + SA_L + (r0 + 8) * SROWB + kc * 2);
                al[mt][2] = *(const uint32_t*)(smem + SA_L + (r0    ) * SROWB + (kc + 8) * 2);
                al[mt][3] = *(const uint32_t*)(smem + SA_L + (r0 + 8) * SROWB + (kc + 8) * 2);
            }
            #pragma unroll
            for (int nt = 0; nt < 8; nt++) {
                int n0 = wn * 64 + nt * 8 + gid;
                uint32_t bh0 = *(const uint32_t*)(smem + SB_H + n0 * SROWB + kc * 2);
                uint32_t bh1 = *(const uint32_t*)(smem + SB_H + n0 * SROWB + (kc + 8) * 2);
                uint32_t bl0 = *(const uint32_t*)(smem + SB_L + n0 * SROWB + kc * 2);
                uint32_t bl1 = *(const uint32_t*)(smem + SB_L + n0 * SROWB + (kc + 8) * 2);
                #pragma unroll
                for (int mt = 0; mt < 2; mt++) {
                    mma_bf16(acc[mt][nt], ah[mt], bh0, bh1);
                    mma_bf16(acc[mt][nt], al[mt], bh0, bh1);
                    mma_bf16(acc[mt][nt], ah[mt], bl0, bl1);
                }
            }
        }
    }

    __syncthreads();
    float* Cs = (float*)smem;
    #pragma unroll
    for (int mt = 0; mt < 2; mt++) {
        #pragma unroll
        for (int nt = 0; nt < 8; nt++) {
            int r0 = wm * 32 + mt * 16 + gid;
            int c0 = wn * 64 + nt * 8 + qid * 2;
            Cs[(r0    ) * CPAD + c0    ] = acc[mt][nt][0];
            Cs[(r0    ) * CPAD + c0 + 1] = acc[mt][nt][1];
            Cs[(r0 + 8) * CPAD + c0    ] = acc[mt][nt][2];
            Cs[(r0 + 8) * CPAD + c0 + 1] = acc[mt][nt][3];
        }
    }
    __syncthreads();

    for (int rr = wid * 16; rr < wid * 16 + 16; rr++) {
        int row = tile * 128 + rr;
        int c = lane * 4;
        if (MODE == 1 && row >= N && row < rowsTot) {
            __nv_bfloat162 z; z.x = __float2bfloat16(0.f); z.y = z.x;
            size_t off = (size_t)row * 256 + c;
            *(__nv_bfloat162*)&A2hi[off] = z; *(__nv_bfloat162*)&A2hi[off + 2] = z;
            *(__nv_bfloat162*)&A2lo[off] = z; *(__nv_bfloat162*)&A2lo[off + 2] = z;
            continue;
        }
        if (row >= N) continue;
        float4 v = *(const float4*)&Cs[rr * CPAD + c];
        float4 bv = *(const float4*)&bias[c];
        v.x += bv.x; v.y += bv.y; v.z += bv.z; v.w += bv.w;

        if (MODE == 0) {
            float s = v.x + v.y + v.z + v.w;
            float sq = v.x * v.x + v.y * v.y + v.z * v.z + v.w * v.w;
            #pragma unroll
            for (int o = 16; o; o >>= 1) {
                s  += __shfl_xor_sync(0xffffffffu, s,  o);
                sq += __shfl_xor_sync(0xffffffffu, sq, o);
            }
            float mu = s * (1.f / 128.f);
            float var = sq * (1.f / 128.f) - mu * mu;
            float r = rsqrtf(var + 1e-5f);
            float4 gv = *(const float4*)&ln_g[c];
            float4 lb = *(const float4*)&ln_b[c];
            float4 o;
            o.x = fmaxf((v.x - mu) * r * gv.x + lb.x, 0.f);
            o.y = fmaxf((v.y - mu) * r * gv.y + lb.y, 0.f);
            o.z = fmaxf((v.z - mu) * r * gv.z + lb.z, 0.f);
            o.w = fmaxf((v.w - mu) * r * gv.w + lb.w, 0.f);
            *(float4*)&O0[(size_t)row * 128 + c] = o;
        } else if (MODE == 1) {
            *(float4*)&O0[(size_t)row * 128 + c] = v;
            __nv_bfloat16 a, b;
            __nv_bfloat162 hh0, hh1, ll0, ll1;
            split_bf16(v.x, a, b); hh0.x = a; ll0.x = b;
            split_bf16(v.y, a, b); hh0.y = a; ll0.y = b;
            split_bf16(v.z, a, b); hh1.x = a; ll1.x = b;
            split_bf16(v.w, a, b); hh1.y = a; ll1.y = b;
            size_t off = (size_t)row * 256 + c;
            *(__nv_bfloat162*)&A2hi[off] = hh0; *(__nv_bfloat162*)&A2hi[off + 2] = hh1;
            *(__nv_bfloat162*)&A2lo[off] = ll0; *(__nv_bfloat162*)&A2lo[off + 2] = ll1;
        } else {
            float4 sv = *(const float4*)&std_in[(size_t)row * 128 + c];
            float4 cv = *(const float4*)&conv_in[(size_t)row * 128 + c];
            float4 o; float g;
            g = 1.f / (1.f + expf(-v.x)); o.x = g * sv.x + (1.f - g) * cv.x;
            g = 1.f / (1.f + expf(-v.y)); o.y = g * sv.y + (1.f - g) * cv.y;
            g = 1.f / (1.f + expf(-v.z)); o.z = g * sv.z + (1.f - g) * cv.z;
            g = 1.f / (1.f + expf(-v.w)); o.w = g * sv.w + (1.f - g) * cv.w;
            *(float4*)&O0[(size_t)row * 128 + c] = o;
        }
    }
}

// ================= launch =================
extern "C" void kernel_launch(void* const* d_in, const int* in_sizes, int n_in,
                              void* d_out, int out_size)
{
    const float* h      = (const float*)d_in[0];
    const float* ctx    = (const float*)d_in[1];
    const int*   src    = (const int*)  d_in[2];
    const int*   dst    = (const int*)  d_in[3];
    const float* W_self = (const float*)d_in[4];
    const float* W_neigh= (const float*)d_in[5];
    const float* b_sage = (const float*)d_in[6];
    const float* Wm     = (const float*)d_in[7];
    const float* bm     = (const float*)d_in[8];
    const float* ln_g   = (const float*)d_in[9];
    const float* ln_b   = (const float*)d_in[10];
    const float* Wg     = (const float*)d_in[11];
    const float* bg     = (const float*)d_in[12];
    float* out = (float*)d_out;

    int N = in_sizes[0] / 128;
    if (N < 1) N = 1;
    if (N > MAXN) N = MAXN;
    int E = in_sizes[2];
    int tiles = (N + 127) / 128;
    int rowsTot = tiles * 128;

    // resolve device addresses of __device__ symbols (GB300/ATS pitfall)
    float *p_conv, *p_m, *p_std;
    __nv_bfloat16 *pA0h, *pA0l, *pA2h, *pA2l, *pBh, *pBl;
    cudaGetSymbolAddress((void**)&p_conv,  g_conv);
    cudaGetSymbolAddress((void**)&p_m,     g_m);
    cudaGetSymbolAddress((void**)&p_std,   g_std);
    cudaGetSymbolAddress((void**)&pA0h,    g_A0hi);
    cudaGetSymbolAddress((void**)&pA0l,    g_A0lo);
    cudaGetSymbolAddress((void**)&pA2h,    g_A2hi);
    cudaGetSymbolAddress((void**)&pA2l,    g_A2lo);
    cudaGetSymbolAddress((void**)&pBh,     g_Bhi);
    cudaGetSymbolAddress((void**)&pBl,     g_Blo);

    cudaFuncSetAttribute(mma_k<0>, cudaFuncAttributeMaxDynamicSharedMemorySize, SM_TOTAL);
    cudaFuncSetAttribute(mma_k<1>, cudaFuncAttributeMaxDynamicSharedMemorySize, SM_TOTAL);
    cudaFuncSetAttribute(mma_k<2>, cudaFuncAttributeMaxDynamicSharedMemorySize, SM_TOTAL);

    // ---- CSR build ----
    zero_small_k<<<(MAXN + 255) / 256, 256>>>();
    count_k<<<(E + 255) / 256, 256>>>(dst, E, N);
    scan1_k<<<MAXN / 256, 256>>>();
    scan2_k<<<1, 256>>>(MAXN / 256);
    scan3_k<<<(MAXN + 255) / 256, 256>>>();
    fill_k<<<(E + 255) / 256, 256>>>(src, dst, E, N);

    // ---- operand conversion ----
    convW3_k<<<(3 * 128 * 256 + 255) / 256, 256>>>(Wm, W_self, W_neigh, Wg);
    convA2_k<<<(rowsTot * 128 + 255) / 256, 256>>>(h, ctx, pA0h, pA0l, N, rowsTot);

    // ---- GEMM0 + fused LN/ReLU -> g_m ----
    mma_k<0><<<tiles, 256, SM_TOTAL>>>(pA0h, pA0l, pBh + 0 * 32768, pBl + 0 * 32768, bm, ln_g, ln_b,
                                       p_m, nullptr, nullptr, nullptr, nullptr, N, rowsTot);

    // ---- CSR aggregation: fills A0[:,128:256], A2[:,128:256], g_conv ----
    agg_k<<<(rowsTot * 32 + 255) / 256, 256>>>(h, pA0h, pA0l, pA2h, pA2l, p_conv, rowsTot);

    // ---- GEMM1 -> g_std (+ split into A2 first half) ----
    mma_k<1><<<tiles, 256, SM_TOTAL>>>(pA0h, pA0l, pBh + 1 * 32768, pBl + 1 * 32768, b_sage,
                                       nullptr, nullptr, p_std, pA2h, pA2l, nullptr, nullptr, N, rowsTot);
    // ---- GEMM2 + fused sigmoid/blend -> out ----
    mma_k<2><<<tiles, 256, SM_TOTAL>>>(pA2h, pA2l, pBh + 2 * 32768, pBl + 2 * 32768, bg,
                                       nullptr, nullptr, out, nullptr, nullptr, p_std, p_conv, N, rowsTot);
}

// round 12
// speedup vs baseline: 3.2449x; 1.2823x over previous
#include <cuda_runtime.h>
#include <cuda_bf16.h>
#include <cstdint>

#define DD 128
#define MAXN 50176            // >= N, multiple of 256
#define MAXTILES (MAXN / 128) // 392
#define MAXE (1 << 20)

// ---------------- scratch (static __device__; allocation-free) ----------------
__device__ __align__(128) int   g_cnt[MAXN];
__device__ __align__(128) int   g_cur[MAXN];
__device__ __align__(128) int   g_off[MAXN + 1];
__device__ __align__(128) int   g_bsum[256];
__device__ __align__(128) int   g_bpre[256];
__device__            int   g_total;
__device__ __align__(128) int   g_csr[MAXE];
__device__ __align__(128) float g_conv [MAXN * DD];   // conv_agg (mean-scaled)
__device__ __align__(128) float g_m    [MAXN * DD];
__device__ __align__(128) float g_std  [MAXN * DD];
// bf16 split operand buffers, ROW-MAJOR [rows x 256]
__device__ __align__(128) __nv_bfloat16 g_A0hi[MAXN * 256];
__device__ __align__(128) __nv_bfloat16 g_A0lo[MAXN * 256];
__device__ __align__(128) __nv_bfloat16 g_A2hi[MAXN * 256];
__device__ __align__(128) __nv_bfloat16 g_A2lo[MAXN * 256];
// weight tiles: Bt row-major [128 n x 256 k], 3 gemms x hi/lo
__device__ __align__(128) __nv_bfloat16 g_Bhi[3][128 * 256];
__device__ __align__(128) __nv_bfloat16 g_Blo[3][128 * 256];

// ---------------- helpers ----------------
__device__ __forceinline__ void split_bf16(float f, __nv_bfloat16& h, __nv_bfloat16& l) {
    h = __float2bfloat16(f);
    l = __float2bfloat16(f - __bfloat162float(h));
}
__device__ __forceinline__ void mma_bf16(float* d, const uint32_t* a, uint32_t b0, uint32_t b1) {
    asm volatile("mma.sync.aligned.m16n8k16.row.col.f32.bf16.bf16.f32 "
                 "{%0,%1,%2,%3}, {%4,%5,%6,%7}, {%8,%9}, {%0,%1,%2,%3};"
                 : "+f"(d[0]), "+f"(d[1]), "+f"(d[2]), "+f"(d[3])
                 : "r"(a[0]), "r"(a[1]), "r"(a[2]), "r"(a[3]), "r"(b0), "r"(b1));
}
__device__ __forceinline__ uint32_t smem_u32(const void* p) {
    uint32_t a;
    asm("{ .reg .u64 t; cvta.to.shared.u64 t, %1; cvt.u32.u64 %0, t; }" : "=r"(a) : "l"(p));
    return a;
}
__device__ __forceinline__ void cp_async16(uint32_t dst, const void* src) {
    asm volatile("cp.async.ca.shared.global [%0], [%1], 16;" :: "r"(dst), "l"(src));
}
__device__ __forceinline__ void cp_commit() { asm volatile("cp.async.commit_group;" ::: "memory"); }
template<int W> __device__ __forceinline__ void cp_wait() {
    asm volatile("cp.async.wait_group %0;" :: "n"(W) : "memory");
}
__device__ __forceinline__ void ldsm_x4(uint32_t* r, uint32_t addr) {
    asm volatile("ldmatrix.sync.aligned.m8n8.x4.shared.b16 {%0,%1,%2,%3}, [%4];"
                 : "=r"(r[0]), "=r"(r[1]), "=r"(r[2]), "=r"(r[3]) : "r"(addr));
}

// ================= fused init: zero counters + convW3 + convA2 =================
__global__ void init_k(const float* __restrict__ Wm, const float* __restrict__ W_self,
                       const float* __restrict__ W_neigh, const float* __restrict__ Wg,
                       const float* __restrict__ h, const float* __restrict__ ctx,
                       __nv_bfloat16* __restrict__ A0h, __nv_bfloat16* __restrict__ A0l,
                       int N, int rowsTot)
{
    int i = blockIdx.x * blockDim.x + threadIdx.x;
    if (i < 3 * 32768) {
        // weights -> transposed + split
        int g = i >> 15;
        int r = i & 32767;
        int n = r >> 8, k = r & 255;
        float w;
        if (g == 0)      w = Wm[k * 128 + n];
        else if (g == 1) w = (k < 128) ? W_self[k * 128 + n] : W_neigh[(k - 128) * 128 + n];
        else             w = Wg[k * 128 + n];
        __nv_bfloat16 hh, ll; split_bf16(w, hh, ll);
        g_Bhi[g][n * 256 + k] = hh;
        g_Blo[g][n * 256 + k] = ll;
        return;
    }
    i -= 3 * 32768;
    if (i < MAXN) { g_cnt[i] = 0; g_cur[i] = 0; return; }
    i -= MAXN;
    if (i >= rowsTot * 128) return;
    // A0 = split([h | ctx])
    int r = i >> 7;
    int cp = (i & 127) * 2;
    float2 v = make_float2(0.f, 0.f);
    if (r < N) {
        const float* S = (cp < 128) ? h : ctx;
        int c = cp & 127;
        v = *(const float2*)&S[(size_t)r * 128 + c];
    }
    __nv_bfloat16 h0, l0, h1, l1;
    split_bf16(v.x, h0, l0);
    split_bf16(v.y, h1, l1);
    size_t off = (size_t)r * 256 + cp;
    __nv_bfloat162 hh; hh.x = h0; hh.y = h1;
    __nv_bfloat162 ll; ll.x = l0; ll.y = l1;
    *(__nv_bfloat162*)&A0h[off] = hh;
    *(__nv_bfloat162*)&A0l[off] = ll;
}

// ================= CSR build =================
__global__ void count_k(const int* __restrict__ dst, int E, int N) {
    int i = blockIdx.x * blockDim.x + threadIdx.x;
    if (i < E) {
        int d = dst[i];
        d = min(max(d, 0), N - 1);
        atomicAdd(&g_cnt[d], 1);
    }
}
__global__ void scan1_k() {
    __shared__ int sm[256];
    int b = blockIdx.x, t = threadIdx.x;
    int v = g_cnt[b * 256 + t];
    sm[t] = v;
    __syncthreads();
    int acc = v;
    #pragma unroll
    for (int o = 1; o < 256; o <<= 1) {
        int p = (t >= o) ? sm[t - o] : 0;
        __syncthreads();
        acc += p; sm[t] = acc;
        __syncthreads();
    }
    g_off[b * 256 + t] = acc - v;
    if (t == 255) g_bsum[b] = acc;
}
__global__ void scan2_k(int nb) {
    __shared__ int sm[256];
    int t = threadIdx.x;
    int v = (t < nb) ? g_bsum[t] : 0;
    sm[t] = v;
    __syncthreads();
    int acc = v;
    #pragma unroll
    for (int o = 1; o < 256; o <<= 1) {
        int p = (t >= o) ? sm[t - o] : 0;
        __syncthreads();
        acc += p; sm[t] = acc;
        __syncthreads();
    }
    g_bpre[t] = acc - v;
    if (t == 255) g_total = acc;
}
__global__ void scan3_k() {
    int i = blockIdx.x * blockDim.x + threadIdx.x;
    if (i < MAXN) g_off[i] += g_bpre[i >> 8];
    if (i == 0) g_off[MAXN] = g_total;
}
__global__ void fill_k(const int* __restrict__ src, const int* __restrict__ dst, int E, int N) {
    int i = blockIdx.x * blockDim.x + threadIdx.x;
    if (i >= E) return;
    int d = dst[i];
    d = min(max(d, 0), N - 1);
    int pos = g_off[d] + atomicAdd(&g_cur[d], 1);
    if (pos < MAXE) {
        int s = src[i];
        g_csr[pos] = min(max(s, 0), N - 1);
    }
}

// ================= CSR aggregation (atomic-free) =================
__global__ void agg_k(const float* __restrict__ h,
                      __nv_bfloat16* __restrict__ A0h, __nv_bfloat16* __restrict__ A0l,
                      __nv_bfloat16* __restrict__ A2h, __nv_bfloat16* __restrict__ A2l,
                      float* __restrict__ conv_out, int rowsTot)
{
    int d = (blockIdx.x * blockDim.x + threadIdx.x) >> 5;
    int lane = threadIdx.x & 31;
    if (d >= rowsTot) return;
    int e0 = g_off[d], e1 = g_off[d + 1];
    int cnt = e1 - e0;
    float4 sh = make_float4(0.f, 0.f, 0.f, 0.f);
    float4 sm = make_float4(0.f, 0.f, 0.f, 0.f);
    for (int e = e0; e < e1; e++) {
        int s = g_csr[e];
        size_t so = (size_t)s * 128 + lane * 4;
        float4 vh = *(const float4*)&h[so];
        float4 vm = *(const float4*)&g_m[so];
        sh.x += vh.x; sh.y += vh.y; sh.z += vh.z; sh.w += vh.w;
        sm.x += vm.x; sm.y += vm.y; sm.z += vm.z; sm.w += vm.w;
    }
    float iv = 1.0f / fmaxf((float)cnt, 1.0f);
    sh.x *= iv; sh.y *= iv; sh.z *= iv; sh.w *= iv;
    sm.x *= iv; sm.y *= iv; sm.z *= iv; sm.w *= iv;

    *(float4*)&conv_out[(size_t)d * 128 + lane * 4] = sm;

    size_t off = (size_t)d * 256 + 128 + lane * 4;
    __nv_bfloat16 a, b;
    __nv_bfloat162 hh0, hh1, ll0, ll1;
    split_bf16(sh.x, a, b); hh0.x = a; ll0.x = b;
    split_bf16(sh.y, a, b); hh0.y = a; ll0.y = b;
    split_bf16(sh.z, a, b); hh1.x = a; ll1.x = b;
    split_bf16(sh.w, a, b); hh1.y = a; ll1.y = b;
    *(__nv_bfloat162*)&A0h[off] = hh0; *(__nv_bfloat162*)&A0h[off + 2] = hh1;
    *(__nv_bfloat162*)&A0l[off] = ll0; *(__nv_bfloat162*)&A0l[off + 2] = ll1;
    split_bf16(sm.x, a, b); hh0.x = a; ll0.x = b;
    split_bf16(sm.y, a, b); hh0.y = a; ll0.y = b;
    split_bf16(sm.z, a, b); hh1.x = a; ll1.x = b;
    split_bf16(sm.w, a, b); hh1.y = a; ll1.y = b;
    *(__nv_bfloat162*)&A2h[off] = hh0; *(__nv_bfloat162*)&A2h[off + 2] = hh1;
    *(__nv_bfloat162*)&A2l[off] = ll0; *(__nv_bfloat162*)&A2l[off + 2] = ll1;
}

// ================= HMMA GEMM: 2-stage cp.async pipeline + ldmatrix ==================
#define SPAD 40
#define SROWB (SPAD * 2)                // 80 bytes per smem row (16B-aligned, conflict-free)
#define O_AH 0
#define O_AL 10240
#define O_BH 20480
#define O_BL 30720
#define STAGE_BYTES 40960
#define CPAD 132
#define SM_TOTAL (2 * STAGE_BYTES)      // 81920; C staging (67584) reuses stage 0/1

// MODE 0: O0 = relu(LN(D + bias)) with ln_g/ln_b
// MODE 1: O0 = D + bias; split(O0) -> A2 cols [0,128); zero-fill A2 rows [N,rowsTot)
// MODE 2: out = sig(D+bias)*std_in + (1-sig)*conv_in   (conv_in pre-scaled)
template<int MODE>
__global__ __launch_bounds__(256, 2)
void mma_k(const __nv_bfloat16* __restrict__ Ahi, const __nv_bfloat16* __restrict__ Alo,
           const __nv_bfloat16* __restrict__ Bhi, const __nv_bfloat16* __restrict__ Blo,
           const float* __restrict__ bias,
           const float* __restrict__ ln_g, const float* __restrict__ ln_b,
           float* __restrict__ O0,
           __nv_bfloat16* __restrict__ A2hi, __nv_bfloat16* __restrict__ A2lo,
           const float* __restrict__ std_in, const float* __restrict__ conv_in,
           int N, int rowsTot)
{
    extern __shared__ __align__(16) char smem[];
    uint32_t sb = smem_u32(smem);
    int tid = threadIdx.x;
    int lane = tid & 31, wid = tid >> 5;
    int wm = wid & 3, wn = wid >> 2;     // warp grid 4 (rows) x 2 (cols)
    int tile = blockIdx.x;

    const __nv_bfloat16* gAh = Ahi + (size_t)tile * 128 * 256;
    const __nv_bfloat16* gAl = Alo + (size_t)tile * 128 * 256;

    float acc[2][8][4];
    #pragma unroll
    for (int mt = 0; mt < 2; mt++)
        #pragma unroll
        for (int nt = 0; nt < 8; nt++)
            #pragma unroll
            for (int q = 0; q < 4; q++) acc[mt][nt][q] = 0.f;

    // per-thread copy slots: 2 x (row, 16B-quarter) covering 128x32 bf16 per matrix
    int cr0 = tid >> 2, cc0 = (tid & 3) * 16;
    int cr1 = (tid + 256) >> 2, cc1 = ((tid + 256) & 3) * 16;

    auto load_chunk = [&](int ch) {
        uint32_t base = sb + (uint32_t)(ch & 1) * STAGE_BYTES;
        size_t g0 = (size_t)cr0 * 256 + ch * 32;   // + col bytes/2
        size_t g1 = (size_t)cr1 * 256 + ch * 32;
        uint32_t s0 = base + cr0 * SROWB;
        uint32_t s1 = base + cr1 * SROWB;
        cp_async16(s0 + O_AH + cc0, (const char*)gAh + g0 * 2 + cc0);
        cp_async16(s1 + O_AH + cc1, (const char*)gAh + g1 * 2 + cc1);
        cp_async16(s0 + O_AL + cc0, (const char*)gAl + g0 * 2 + cc0);
        cp_async16(s1 + O_AL + cc1, (const char*)gAl + g1 * 2 + cc1);
        cp_async16(s0 + O_BH + cc0, (const char*)Bhi + g0 * 2 + cc0);
        cp_async16(s1 + O_BH + cc1, (const char*)Bhi + g1 * 2 + cc1);
        cp_async16(s0 + O_BL + cc0, (const char*)Blo + g0 * 2 + cc0);
        cp_async16(s1 + O_BL + cc1, (const char*)Blo + g1 * 2 + cc1);
        cp_commit();
    };

    load_chunk(0);
    for (int ch = 0; ch < 8; ch++) {
        if (ch < 7) { load_chunk(ch + 1); cp_wait<1>(); }
        else        { cp_wait<0>(); }
        __syncthreads();
        uint32_t base = sb + (uint32_t)(ch & 1) * STAGE_BYTES;

        // ldmatrix address components
        int arow = wm * 32 + (lane & 7) + (lane & 8);       // + mt*16
        int acolh = ((lane >> 4) << 3);                     // + kk
        int brow_base = wn * 64 + ((lane >> 4) << 3) + (lane & 7);  // + p*16
        int bcol_sel = (((lane >> 3) & 1) << 3);            // + kk

        #pragma unroll
        for (int kk = 0; kk < 32; kk += 16) {
            uint32_t ah[2][4], al[2][4];
            #pragma unroll
            for (int mt = 0; mt < 2; mt++) {
                uint32_t ao = (uint32_t)(arow + mt * 16) * SROWB + (uint32_t)(kk + acolh) * 2;
                ldsm_x4(ah[mt], base + O_AH + ao);
                ldsm_x4(al[mt], base + O_AL + ao);
            }
            #pragma unroll
            for (int p = 0; p < 4; p++) {
                uint32_t bo = (uint32_t)(brow_base + p * 16) * SROWB + (uint32_t)(kk + bcol_sel) * 2;
                uint32_t bh[4], bl[4];
                ldsm_x4(bh, base + O_BH + bo);
                ldsm_x4(bl, base + O_BL + bo);
                #pragma unroll
                for (int sub = 0; sub < 2; sub++) {
                    int nt = p * 2 + sub;
                    #pragma unroll
                    for (int mt = 0; mt < 2; mt++) {
                        mma_bf16(acc[mt][nt], ah[mt], bh[sub * 2], bh[sub * 2 + 1]);
                        mma_bf16(acc[mt][nt], al[mt], bh[sub * 2], bh[sub * 2 + 1]);
                        mma_bf16(acc[mt][nt], ah[mt], bl[sub * 2], bl[sub * 2 + 1]);
                    }
                }
            }
        }
        __syncthreads();
    }

    // ---- stage C to smem ----
    int gid = lane >> 2, qid = lane & 3;
    float* Cs = (float*)smem;
    #pragma unroll
    for (int mt = 0; mt < 2; mt++) {
        #pragma unroll
        for (int nt = 0; nt < 8; nt++) {
            int r0 = wm * 32 + mt * 16 + gid;
            int c0 = wn * 64 + nt * 8 + qid * 2;
            Cs[(r0    ) * CPAD + c0    ] = acc[mt][nt][0];
            Cs[(r0    ) * CPAD + c0 + 1] = acc[mt][nt][1];
            Cs[(r0 + 8) * CPAD + c0    ] = acc[mt][nt][2];
            Cs[(r0 + 8) * CPAD + c0 + 1] = acc[mt][nt][3];
        }
    }
    __syncthreads();

    for (int rr = wid * 16; rr < wid * 16 + 16; rr++) {
        int row = tile * 128 + rr;
        int c = lane * 4;
        if (MODE == 1 && row >= N && row < rowsTot) {
            __nv_bfloat162 z; z.x = __float2bfloat16(0.f); z.y = z.x;
            size_t off = (size_t)row * 256 + c;
            *(__nv_bfloat162*)&A2hi[off] = z; *(__nv_bfloat162*)&A2hi[off + 2] = z;
            *(__nv_bfloat162*)&A2lo[off] = z; *(__nv_bfloat162*)&A2lo[off + 2] = z;
            continue;
        }
        if (row >= N) continue;
        float4 v = *(const float4*)&Cs[rr * CPAD + c];
        float4 bv = *(const float4*)&bias[c];
        v.x += bv.x; v.y += bv.y; v.z += bv.z; v.w += bv.w;

        if (MODE == 0) {
            float s = v.x + v.y + v.z + v.w;
            float sq = v.x * v.x + v.y * v.y + v.z * v.z + v.w * v.w;
            #pragma unroll
            for (int o = 16; o; o >>= 1) {
                s  += __shfl_xor_sync(0xffffffffu, s,  o);
                sq += __shfl_xor_sync(0xffffffffu, sq, o);
            }
            float mu = s * (1.f / 128.f);
            float var = sq * (1.f / 128.f) - mu * mu;
            float r = rsqrtf(var + 1e-5f);
            float4 gv = *(const float4*)&ln_g[c];
            float4 lb = *(const float4*)&ln_b[c];
            float4 o;
            o.x = fmaxf((v.x - mu) * r * gv.x + lb.x, 0.f);
            o.y = fmaxf((v.y - mu) * r * gv.y + lb.y, 0.f);
            o.z = fmaxf((v.z - mu) * r * gv.z + lb.z, 0.f);
            o.w = fmaxf((v.w - mu) * r * gv.w + lb.w, 0.f);
            *(float4*)&O0[(size_t)row * 128 + c] = o;
        } else if (MODE == 1) {
            *(float4*)&O0[(size_t)row * 128 + c] = v;
            __nv_bfloat16 a, b;
            __nv_bfloat162 hh0, hh1, ll0, ll1;
            split_bf16(v.x, a, b); hh0.x = a; ll0.x = b;
            split_bf16(v.y, a, b); hh0.y = a; ll0.y = b;
            split_bf16(v.z, a, b); hh1.x = a; ll1.x = b;
            split_bf16(v.w, a, b); hh1.y = a; ll1.y = b;
            size_t off = (size_t)row * 256 + c;
            *(__nv_bfloat162*)&A2hi[off] = hh0; *(__nv_bfloat162*)&A2hi[off + 2] = hh1;
            *(__nv_bfloat162*)&A2lo[off] = ll0; *(__nv_bfloat162*)&A2lo[off + 2] = ll1;
        } else {
            float4 sv = *(const float4*)&std_in[(size_t)row * 128 + c];
            float4 cv = *(const float4*)&conv_in[(size_t)row * 128 + c];
            float4 o; float g;
            g = 1.f / (1.f + expf(-v.x)); o.x = g * sv.x + (1.f - g) * cv.x;
            g = 1.f / (1.f + expf(-v.y)); o.y = g * sv.y + (1.f - g) * cv.y;
            g = 1.f / (1.f + expf(-v.z)); o.z = g * sv.z + (1.f - g) * cv.z;
            g = 1.f / (1.f + expf(-v.w)); o.w = g * sv.w + (1.f - g) * cv.w;
            *(float4*)&O0[(size_t)row * 128 + c] = o;
        }
    }
}

// ================= launch =================
extern "C" void kernel_launch(void* const* d_in, const int* in_sizes, int n_in,
                              void* d_out, int out_size)
{
    const float* h      = (const float*)d_in[0];
    const float* ctx    = (const float*)d_in[1];
    const int*   src    = (const int*)  d_in[2];
    const int*   dst    = (const int*)  d_in[3];
    const float* W_self = (const float*)d_in[4];
    const float* W_neigh= (const float*)d_in[5];
    const float* b_sage = (const float*)d_in[6];
    const float* Wm     = (const float*)d_in[7];
    const float* bm     = (const float*)d_in[8];
    const float* ln_g   = (const float*)d_in[9];
    const float* ln_b   = (const float*)d_in[10];
    const float* Wg     = (const float*)d_in[11];
    const float* bg     = (const float*)d_in[12];
    float* out = (float*)d_out;

    int N = in_sizes[0] / 128;
    if (N < 1) N = 1;
    if (N > MAXN) N = MAXN;
    int E = in_sizes[2];
    int tiles = (N + 127) / 128;
    int rowsTot = tiles * 128;

    // resolve device addresses of __device__ symbols (GB300/ATS pitfall)
    float *p_conv, *p_m, *p_std;
    __nv_bfloat16 *pA0h, *pA0l, *pA2h, *pA2l, *pBh, *pBl;
    cudaGetSymbolAddress((void**)&p_conv,  g_conv);
    cudaGetSymbolAddress((void**)&p_m,     g_m);
    cudaGetSymbolAddress((void**)&p_std,   g_std);
    cudaGetSymbolAddress((void**)&pA0h,    g_A0hi);
    cudaGetSymbolAddress((void**)&pA0l,    g_A0lo);
    cudaGetSymbolAddress((void**)&pA2h,    g_A2hi);
    cudaGetSymbolAddress((void**)&pA2l,    g_A2lo);
    cudaGetSymbolAddress((void**)&pBh,     g_Bhi);
    cudaGetSymbolAddress((void**)&pBl,     g_Blo);

    cudaFuncSetAttribute(mma_k<0>, cudaFuncAttributeMaxDynamicSharedMemorySize, SM_TOTAL);
    cudaFuncSetAttribute(mma_k<1>, cudaFuncAttributeMaxDynamicSharedMemorySize, SM_TOTAL);
    cudaFuncSetAttribute(mma_k<2>, cudaFuncAttributeMaxDynamicSharedMemorySize, SM_TOTAL);

    // 1) fused init: convW3 + zero counters + convA2
    int init_threads = 3 * 32768 + MAXN + rowsTot * 128;
    init_k<<<(init_threads + 255) / 256, 256>>>(Wm, W_self, W_neigh, Wg, h, ctx,
                                                pA0h, pA0l, N, rowsTot);
    // 2) CSR build
    count_k<<<(E + 255) / 256, 256>>>(dst, E, N);
    scan1_k<<<MAXN / 256, 256>>>();
    scan2_k<<<1, 256>>>(MAXN / 256);
    scan3_k<<<(MAXN + 255) / 256, 256>>>();
    fill_k<<<(E + 255) / 256, 256>>>(src, dst, E, N);

    // 3) GEMM0 + fused LN/ReLU -> g_m
    mma_k<0><<<tiles, 256, SM_TOTAL>>>(pA0h, pA0l, pBh + 0 * 32768, pBl + 0 * 32768, bm, ln_g, ln_b,
                                       p_m, nullptr, nullptr, nullptr, nullptr, N, rowsTot);
    // 4) CSR aggregation: fills A0[:,128:256], A2[:,128:256], g_conv
    agg_k<<<(rowsTot * 32 + 255) / 256, 256>>>(h, pA0h, pA0l, pA2h, pA2l, p_conv, rowsTot);
    // 5) GEMM1 -> g_std (+ split into A2 first half)
    mma_k<1><<<tiles, 256, SM_TOTAL>>>(pA0h, pA0l, pBh + 1 * 32768, pBl + 1 * 32768, b_sage,
                                       nullptr, nullptr, p_std, pA2h, pA2l, nullptr, nullptr, N, rowsTot);
    // 6) GEMM2 + fused sigmoid/blend -> out
    mma_k<2><<<tiles, 256, SM_TOTAL>>>(pA2h, pA2l, pBh + 2 * 32768, pBl + 2 * 32768, bg,
                                       nullptr, nullptr, out, nullptr, nullptr, p_std, p_conv, N, rowsTot);
}

// round 13
// speedup vs baseline: 3.2735x; 1.0088x over previous
#include <cuda_runtime.h>
#include <cuda_bf16.h>
#include <cstdint>

#define DD 128
#define MAXN 50176            // >= N, multiple of 256 (= 196*256)
#define MAXTILES (MAXN / 128)
#define MAXE (1 << 20)
#define NBLK 196              // scan blocks
#define FILLB 120             // filler blocks appended to mma_k<0>

// ---------------- scratch (static __device__; allocation-free) ----------------
__device__ __align__(128) int   g_cnt[MAXN];        // drained back to 0 by fill each run
__device__ __align__(128) int   g_off[MAXN + 1];
__device__ __align__(128) int   g_blk_state[NBLK];  // (sum<<1)|1 aggregates; zeroed by init each run
__device__ __align__(128) int   g_csr[MAXE];
__device__ __align__(128) float g_conv [MAXN * DD];
__device__ __align__(128) float g_m    [MAXN * DD];
__device__ __align__(128) float g_std  [MAXN * DD];
// bf16 split operand buffers, ROW-MAJOR [rows x 256]
__device__ __align__(128) __nv_bfloat16 g_A0hi[MAXN * 256];
__device__ __align__(128) __nv_bfloat16 g_A0lo[MAXN * 256];
__device__ __align__(128) __nv_bfloat16 g_A2hi[MAXN * 256];
__device__ __align__(128) __nv_bfloat16 g_A2lo[MAXN * 256];
__device__ __align__(128) __nv_bfloat16 g_Bhi[3][128 * 256];
__device__ __align__(128) __nv_bfloat16 g_Blo[3][128 * 256];

// ---------------- helpers ----------------
__device__ __forceinline__ void split_bf16(float f, __nv_bfloat16& h, __nv_bfloat16& l) {
    h = __float2bfloat16(f);
    l = __float2bfloat16(f - __bfloat162float(h));
}
__device__ __forceinline__ void mma_bf16(float* d, const uint32_t* a, uint32_t b0, uint32_t b1) {
    asm volatile("mma.sync.aligned.m16n8k16.row.col.f32.bf16.bf16.f32 "
                 "{%0,%1,%2,%3}, {%4,%5,%6,%7}, {%8,%9}, {%0,%1,%2,%3};"
                 : "+f"(d[0]), "+f"(d[1]), "+f"(d[2]), "+f"(d[3])
                 : "r"(a[0]), "r"(a[1]), "r"(a[2]), "r"(a[3]), "r"(b0), "r"(b1));
}
__device__ __forceinline__ uint32_t smem_u32(const void* p) {
    uint32_t a;
    asm("{ .reg .u64 t; cvta.to.shared.u64 t, %1; cvt.u32.u64 %0, t; }" : "=r"(a) : "l"(p));
    return a;
}
__device__ __forceinline__ void cp_async16(uint32_t dst, const void* src) {
    asm volatile("cp.async.ca.shared.global [%0], [%1], 16;" :: "r"(dst), "l"(src));
}
__device__ __forceinline__ void cp_commit() { asm volatile("cp.async.commit_group;" ::: "memory"); }
template<int W> __device__ __forceinline__ void cp_wait() {
    asm volatile("cp.async.wait_group %0;" :: "n"(W) : "memory");
}
__device__ __forceinline__ void ldsm_x4(uint32_t* r, uint32_t addr) {
    asm volatile("ldmatrix.sync.aligned.m8n8.x4.shared.b16 {%0,%1,%2,%3}, [%4];"
                 : "=r"(r[0]), "=r"(r[1]), "=r"(r[2]), "=r"(r[3]) : "r"(addr));
}

// ===== init: convW3 + zero lookback state + convA2 + edge count (fused) =====
__global__ void init_k(const float* __restrict__ Wm, const float* __restrict__ W_self,
                       const float* __restrict__ W_neigh, const float* __restrict__ Wg,
                       const float* __restrict__ h, const float* __restrict__ ctx,
                       const int* __restrict__ dst,
                       __nv_bfloat16* __restrict__ A0h, __nv_bfloat16* __restrict__ A0l,
                       int E, int N, int rowsTot)
{
    int i = blockIdx.x * blockDim.x + threadIdx.x;
    if (i < 3 * 32768) {
        int g = i >> 15;
        int r = i & 32767;
        int n = r >> 8, k = r & 255;
        float w;
        if (g == 0)      w = Wm[k * 128 + n];
        else if (g == 1) w = (k < 128) ? W_self[k * 128 + n] : W_neigh[(k - 128) * 128 + n];
        else             w = Wg[k * 128 + n];
        __nv_bfloat16 hh, ll; split_bf16(w, hh, ll);
        g_Bhi[g][n * 256 + k] = hh;
        g_Blo[g][n * 256 + k] = ll;
        return;
    }
    i -= 3 * 32768;
    if (i < NBLK) { g_blk_state[i] = 0; return; }
    i -= NBLK;
    if (i < rowsTot * 128) {
        int r = i >> 7;
        int cp = (i & 127) * 2;
        float2 v = make_float2(0.f, 0.f);
        if (r < N) {
            const float* S = (cp < 128) ? h : ctx;
            int c = cp & 127;
            v = *(const float2*)&S[(size_t)r * 128 + c];
        }
        __nv_bfloat16 h0, l0, h1, l1;
        split_bf16(v.x, h0, l0);
        split_bf16(v.y, h1, l1);
        size_t off = (size_t)r * 256 + cp;
        __nv_bfloat162 hh; hh.x = h0; hh.y = h1;
        __nv_bfloat162 ll; ll.x = l0; ll.y = l1;
        *(__nv_bfloat162*)&A0h[off] = hh;
        *(__nv_bfloat162*)&A0l[off] = ll;
        return;
    }
    i -= rowsTot * 128;
    if (i < E) {
        int d = dst[i];
        d = min(max(d, 0), N - 1);
        atomicAdd(&g_cnt[d], 1);   // g_cnt is all-zero at entry (drained by fill each run)
    }
}

// ===== single-kernel exclusive scan with aggregate lookback (196 blocks resident) =====
__global__ void scan_k() {
    __shared__ int sm[256];
    __shared__ int s_prefix;
    int b = blockIdx.x, t = threadIdx.x, lane = t & 31;
    int v = g_cnt[b * 256 + t];
    sm[t] = v;
    __syncthreads();
    int acc = v;
    #pragma unroll
    for (int o = 1; o < 256; o <<= 1) {
        int p = (t >= o) ? sm[t - o] : 0;
        __syncthreads();
        acc += p; sm[t] = acc;
        __syncthreads();
    }
    int total = sm[255];
    if (t == 0) atomicExch(&g_blk_state[b], (total << 1) | 1);
    if (t < 32) {
        int prefix = 0;
        for (int base = 0; base < b; base += 32) {
            int idx = base + lane;
            int st = 0;
            if (idx < b) {
                do { st = atomicAdd(&g_blk_state[idx], 0); } while ((st & 1) == 0);
            }
            int c = (idx < b) ? (st >> 1) : 0;
            #pragma unroll
            for (int o = 16; o; o >>= 1) c += __shfl_xor_sync(0xffffffffu, c, o);
            prefix += c;
        }
        if (lane == 0) s_prefix = prefix;
    }
    __syncthreads();
    g_off[b * 256 + t] = s_prefix + acc - v;
    if (b == NBLK - 1 && t == 255) g_off[MAXN] = s_prefix + acc;
}

// ===== CSR aggregation (atomic-free, unroll x2) =====
__global__ void agg_k(const float* __restrict__ h,
                      __nv_bfloat16* __restrict__ A0h, __nv_bfloat16* __restrict__ A0l,
                      __nv_bfloat16* __restrict__ A2h, __nv_bfloat16* __restrict__ A2l,
                      float* __restrict__ conv_out, int rowsTot)
{
    int d = (blockIdx.x * blockDim.x + threadIdx.x) >> 5;
    int lane = threadIdx.x & 31;
    if (d >= rowsTot) return;
    int e0 = g_off[d], e1 = g_off[d + 1];
    int cnt = e1 - e0;
    float4 sh = make_float4(0.f, 0.f, 0.f, 0.f);
    float4 sm = make_float4(0.f, 0.f, 0.f, 0.f);
    int e = e0;
    for (; e + 1 < e1; e += 2) {
        int s0 = g_csr[e], s1 = g_csr[e + 1];
        size_t o0 = (size_t)s0 * 128 + lane * 4;
        size_t o1 = (size_t)s1 * 128 + lane * 4;
        float4 vh0 = *(const float4*)&h[o0];
        float4 vm0 = *(const float4*)&g_m[o0];
        float4 vh1 = *(const float4*)&h[o1];
        float4 vm1 = *(const float4*)&g_m[o1];
        sh.x += vh0.x + vh1.x; sh.y += vh0.y + vh1.y; sh.z += vh0.z + vh1.z; sh.w += vh0.w + vh1.w;
        sm.x += vm0.x + vm1.x; sm.y += vm0.y + vm1.y; sm.z += vm0.z + vm1.z; sm.w += vm0.w + vm1.w;
    }
    if (e < e1) {
        int s0 = g_csr[e];
        size_t o0 = (size_t)s0 * 128 + lane * 4;
        float4 vh0 = *(const float4*)&h[o0];
        float4 vm0 = *(const float4*)&g_m[o0];
        sh.x += vh0.x; sh.y += vh0.y; sh.z += vh0.z; sh.w += vh0.w;
        sm.x += vm0.x; sm.y += vm0.y; sm.z += vm0.z; sm.w += vm0.w;
    }
    float iv = 1.0f / fmaxf((float)cnt, 1.0f);
    sh.x *= iv; sh.y *= iv; sh.z *= iv; sh.w *= iv;
    sm.x *= iv; sm.y *= iv; sm.z *= iv; sm.w *= iv;

    *(float4*)&conv_out[(size_t)d * 128 + lane * 4] = sm;

    size_t off = (size_t)d * 256 + 128 + lane * 4;
    __nv_bfloat16 a, b;
    __nv_bfloat162 hh0, hh1, ll0, ll1;
    split_bf16(sh.x, a, b); hh0.x = a; ll0.x = b;
    split_bf16(sh.y, a, b); hh0.y = a; ll0.y = b;
    split_bf16(sh.z, a, b); hh1.x = a; ll1.x = b;
    split_bf16(sh.w, a, b); hh1.y = a; ll1.y = b;
    *(__nv_bfloat162*)&A0h[off] = hh0; *(__nv_bfloat162*)&A0h[off + 2] = hh1;
    *(__nv_bfloat162*)&A0l[off] = ll0; *(__nv_bfloat162*)&A0l[off + 2] = ll1;
    split_bf16(sm.x, a, b); hh0.x = a; ll0.x = b;
    split_bf16(sm.y, a, b); hh0.y = a; ll0.y = b;
    split_bf16(sm.z, a, b); hh1.x = a; ll1.x = b;
    split_bf16(sm.w, a, b); hh1.y = a; ll1.y = b;
    *(__nv_bfloat162*)&A2h[off] = hh0; *(__nv_bfloat162*)&A2h[off + 2] = hh1;
    *(__nv_bfloat162*)&A2l[off] = ll0; *(__nv_bfloat162*)&A2l[off + 2] = ll1;
}

// ================= HMMA GEMM (2-stage cp.async + ldmatrix), MODE0 also hosts fill ====
#define SPAD 40
#define SROWB (SPAD * 2)
#define O_AH 0
#define O_AL 10240
#define O_BH 20480
#define O_BL 30720
#define STAGE_BYTES 40960
#define CPAD 132
#define SM_TOTAL (2 * STAGE_BYTES)

// MODE 0: O0 = relu(LN(D + bias)); blocks >= tiles perform CSR fill
// MODE 1: O0 = D + bias; split(O0) -> A2 cols [0,128); zero-fill A2 rows [N,rowsTot)
// MODE 2: out = sig(D+bias)*std_in + (1-sig)*conv_in
template<int MODE>
__global__ __launch_bounds__(256, 2)
void mma_k(const __nv_bfloat16* __restrict__ Ahi, const __nv_bfloat16* __restrict__ Alo,
           const __nv_bfloat16* __restrict__ Bhi, const __nv_bfloat16* __restrict__ Blo,
           const float* __restrict__ bias,
           const float* __restrict__ ln_g, const float* __restrict__ ln_b,
           float* __restrict__ O0,
           __nv_bfloat16* __restrict__ A2hi, __nv_bfloat16* __restrict__ A2lo,
           const float* __restrict__ std_in, const float* __restrict__ conv_in,
           const int* __restrict__ src, const int* __restrict__ dst, int E,
           int N, int rowsTot)
{
    int tid = threadIdx.x;
    int tiles = rowsTot >> 7;
    if (MODE == 0 && (int)blockIdx.x >= tiles) {
        // ---- CSR fill role (runs concurrently with GEMM0 blocks) ----
        int fb = blockIdx.x - tiles;
        for (int i = fb * 256 + tid; i < E; i += FILLB * 256) {
            int d = dst[i];
            d = min(max(d, 0), N - 1);
            int pos = g_off[d] + (atomicSub(&g_cnt[d], 1) - 1);  // drains g_cnt back to 0
            if (pos >= 0 && pos < MAXE) {
                int s = src[i];
                g_csr[pos] = min(max(s, 0), N - 1);
            }
        }
        return;
    }

    extern __shared__ __align__(16) char smem[];
    uint32_t sb = smem_u32(smem);
    int lane = tid & 31, wid = tid >> 5;
    int wm = wid & 3, wn = wid >> 2;
    int tile = blockIdx.x;

    const __nv_bfloat16* gAh = Ahi + (size_t)tile * 128 * 256;
    const __nv_bfloat16* gAl = Alo + (size_t)tile * 128 * 256;

    float acc[2][8][4];
    #pragma unroll
    for (int mt = 0; mt < 2; mt++)
        #pragma unroll
        for (int nt = 0; nt < 8; nt++)
            #pragma unroll
            for (int q = 0; q < 4; q++) acc[mt][nt][q] = 0.f;

    int cr0 = tid >> 2, cc0 = (tid & 3) * 16;
    int cr1 = (tid + 256) >> 2, cc1 = ((tid + 256) & 3) * 16;

    auto load_chunk = [&](int ch) {
        uint32_t base = sb + (uint32_t)(ch & 1) * STAGE_BYTES;
        size_t g0 = (size_t)cr0 * 256 + ch * 32;
        size_t g1 = (size_t)cr1 * 256 + ch * 32;
        uint32_t s0 = base + cr0 * SROWB;
        uint32_t s1 = base + cr1 * SROWB;
        cp_async16(s0 + O_AH + cc0, (const char*)gAh + g0 * 2 + cc0);
        cp_async16(s1 + O_AH + cc1, (const char*)gAh + g1 * 2 + cc1);
        cp_async16(s0 + O_AL + cc0, (const char*)gAl + g0 * 2 + cc0);
        cp_async16(s1 + O_AL + cc1, (const char*)gAl + g1 * 2 + cc1);
        cp_async16(s0 + O_BH + cc0, (const char*)Bhi + g0 * 2 + cc0);
        cp_async16(s1 + O_BH + cc1, (const char*)Bhi + g1 * 2 + cc1);
        cp_async16(s0 + O_BL + cc0, (const char*)Blo + g0 * 2 + cc0);
        cp_async16(s1 + O_BL + cc1, (const char*)Blo + g1 * 2 + cc1);
        cp_commit();
    };

    load_chunk(0);
    for (int ch = 0; ch < 8; ch++) {
        if (ch < 7) { load_chunk(ch + 1); cp_wait<1>(); }
        else        { cp_wait<0>(); }
        __syncthreads();
        uint32_t base = sb + (uint32_t)(ch & 1) * STAGE_BYTES;

        int arow = wm * 32 + (lane & 7) + (lane & 8);
        int acolh = ((lane >> 4) << 3);
        int brow_base = wn * 64 + ((lane >> 4) << 3) + (lane & 7);
        int bcol_sel = (((lane >> 3) & 1) << 3);

        #pragma unroll
        for (int kk = 0; kk < 32; kk += 16) {
            uint32_t ah[2][4], al[2][4];
            #pragma unroll
            for (int mt = 0; mt < 2; mt++) {
                uint32_t ao = (uint32_t)(arow + mt * 16) * SROWB + (uint32_t)(kk + acolh) * 2;
                ldsm_x4(ah[mt], base + O_AH + ao);
                ldsm_x4(al[mt], base + O_AL + ao);
            }
            #pragma unroll
            for (int p = 0; p < 4; p++) {
                uint32_t bo = (uint32_t)(brow_base + p * 16) * SROWB + (uint32_t)(kk + bcol_sel) * 2;
                uint32_t bh[4], bl[4];
                ldsm_x4(bh, base + O_BH + bo);
                ldsm_x4(bl, base + O_BL + bo);
                #pragma unroll
                for (int sub = 0; sub < 2; sub++) {
                    int nt = p * 2 + sub;
                    #pragma unroll
                    for (int mt = 0; mt < 2; mt++) {
                        mma_bf16(acc[mt][nt], ah[mt], bh[sub * 2], bh[sub * 2 + 1]);
                        mma_bf16(acc[mt][nt], al[mt], bh[sub * 2], bh[sub * 2 + 1]);
                        mma_bf16(acc[mt][nt], ah[mt], bl[sub * 2], bl[sub * 2 + 1]);
                    }
                }
            }
        }
        __syncthreads();
    }

    // ---- stage C to smem ----
    int gid = lane >> 2, qid = lane & 3;
    float* Cs = (float*)smem;
    #pragma unroll
    for (int mt = 0; mt < 2; mt++) {
        #pragma unroll
        for (int nt = 0; nt < 8; nt++) {
            int r0 = wm * 32 + mt * 16 + gid;
            int c0 = wn * 64 + nt * 8 + qid * 2;
            Cs[(r0    ) * CPAD + c0    ] = acc[mt][nt][0];
            Cs[(r0    ) * CPAD + c0 + 1] = acc[mt][nt][1];
            Cs[(r0 + 8) * CPAD + c0    ] = acc[mt][nt][2];
            Cs[(r0 + 8) * CPAD + c0 + 1] = acc[mt][nt][3];
        }
    }
    __syncthreads();

    for (int rr = wid * 16; rr < wid * 16 + 16; rr++) {
        int row = tile * 128 + rr;
        int c = lane * 4;
        if (MODE == 1 && row >= N && row < rowsTot) {
            __nv_bfloat162 z; z.x = __float2bfloat16(0.f); z.y = z.x;
            size_t off = (size_t)row * 256 + c;
            *(__nv_bfloat162*)&A2hi[off] = z; *(__nv_bfloat162*)&A2hi[off + 2] = z;
            *(__nv_bfloat162*)&A2lo[off] = z; *(__nv_bfloat162*)&A2lo[off + 2] = z;
            continue;
        }
        if (row >= N) continue;
        float4 v = *(const float4*)&Cs[rr * CPAD + c];
        float4 bv = *(const float4*)&bias[c];
        v.x += bv.x; v.y += bv.y; v.z += bv.z; v.w += bv.w;

        if (MODE == 0) {
            float s = v.x + v.y + v.z + v.w;
            float sq = v.x * v.x + v.y * v.y + v.z * v.z + v.w * v.w;
            #pragma unroll
            for (int o = 16; o; o >>= 1) {
                s  += __shfl_xor_sync(0xffffffffu, s,  o);
                sq += __shfl_xor_sync(0xffffffffu, sq, o);
            }
            float mu = s * (1.f / 128.f);
            float var = sq * (1.f / 128.f) - mu * mu;
            float r = rsqrtf(var + 1e-5f);
            float4 gv = *(const float4*)&ln_g[c];
            float4 lb = *(const float4*)&ln_b[c];
            float4 o;
            o.x = fmaxf((v.x - mu) * r * gv.x + lb.x, 0.f);
            o.y = fmaxf((v.y - mu) * r * gv.y + lb.y, 0.f);
            o.z = fmaxf((v.z - mu) * r * gv.z + lb.z, 0.f);
            o.w = fmaxf((v.w - mu) * r * gv.w + lb.w, 0.f);
            *(float4*)&O0[(size_t)row * 128 + c] = o;
        } else if (MODE == 1) {
            *(float4*)&O0[(size_t)row * 128 + c] = v;
            __nv_bfloat16 a, b;
            __nv_bfloat162 hh0, hh1, ll0, ll1;
            split_bf16(v.x, a, b); hh0.x = a; ll0.x = b;
            split_bf16(v.y, a, b); hh0.y = a; ll0.y = b;
            split_bf16(v.z, a, b); hh1.x = a; ll1.x = b;
            split_bf16(v.w, a, b); hh1.y = a; ll1.y = b;
            size_t off = (size_t)row * 256 + c;
            *(__nv_bfloat162*)&A2hi[off] = hh0; *(__nv_bfloat162*)&A2hi[off + 2] = hh1;
            *(__nv_bfloat162*)&A2lo[off] = ll0; *(__nv_bfloat162*)&A2lo[off + 2] = ll1;
        } else {
            float4 sv = *(const float4*)&std_in[(size_t)row * 128 + c];
            float4 cv = *(const float4*)&conv_in[(size_t)row * 128 + c];
            float4 o; float g;
            g = 1.f / (1.f + expf(-v.x)); o.x = g * sv.x + (1.f - g) * cv.x;
            g = 1.f / (1.f + expf(-v.y)); o.y = g * sv.y + (1.f - g) * cv.y;
            g = 1.f / (1.f + expf(-v.z)); o.z = g * sv.z + (1.f - g) * cv.z;
            g = 1.f / (1.f + expf(-v.w)); o.w = g * sv.w + (1.f - g) * cv.w;
            *(float4*)&O0[(size_t)row * 128 + c] = o;
        }
    }
}

// ================= launch =================
extern "C" void kernel_launch(void* const* d_in, const int* in_sizes, int n_in,
                              void* d_out, int out_size)
{
    const float* h      = (const float*)d_in[0];
    const float* ctx    = (const float*)d_in[1];
    const int*   src    = (const int*)  d_in[2];
    const int*   dst    = (const int*)  d_in[3];
    const float* W_self = (const float*)d_in[4];
    const float* W_neigh= (const float*)d_in[5];
    const float* b_sage = (const float*)d_in[6];
    const float* Wm     = (const float*)d_in[7];
    const float* bm     = (const float*)d_in[8];
    const float* ln_g   = (const float*)d_in[9];
    const float* ln_b   = (const float*)d_in[10];
    const float* Wg     = (const float*)d_in[11];
    const float* bg     = (const float*)d_in[12];
    float* out = (float*)d_out;

    int N = in_sizes[0] / 128;
    if (N < 1) N = 1;
    if (N > MAXN) N = MAXN;
    int E = in_sizes[2];
    int tiles = (N + 127) / 128;
    int rowsTot = tiles * 128;

    // resolve device addresses of __device__ symbols (GB300/ATS pitfall)
    float *p_conv, *p_m, *p_std;
    __nv_bfloat16 *pA0h, *pA0l, *pA2h, *pA2l, *pBh, *pBl;
    cudaGetSymbolAddress((void**)&p_conv,  g_conv);
    cudaGetSymbolAddress((void**)&p_m,     g_m);
    cudaGetSymbolAddress((void**)&p_std,   g_std);
    cudaGetSymbolAddress((void**)&pA0h,    g_A0hi);
    cudaGetSymbolAddress((void**)&pA0l,    g_A0lo);
    cudaGetSymbolAddress((void**)&pA2h,    g_A2hi);
    cudaGetSymbolAddress((void**)&pA2l,    g_A2lo);
    cudaGetSymbolAddress((void**)&pBh,     g_Bhi);
    cudaGetSymbolAddress((void**)&pBl,     g_Blo);

    cudaFuncSetAttribute(mma_k<0>, cudaFuncAttributeMaxDynamicSharedMemorySize, SM_TOTAL);
    cudaFuncSetAttribute(mma_k<1>, cudaFuncAttributeMaxDynamicSharedMemorySize, SM_TOTAL);
    cudaFuncSetAttribute(mma_k<2>, cudaFuncAttributeMaxDynamicSharedMemorySize, SM_TOTAL);

    // 1) fused init: convW3 + zero lookback state + convA2 + count
    int init_threads = 3 * 32768 + NBLK + rowsTot * 128 + E;
    init_k<<<(init_threads + 255) / 256, 256>>>(Wm, W_self, W_neigh, Wg, h, ctx, dst,
                                                pA0h, pA0l, E, N, rowsTot);
    // 2) single-kernel scan -> g_off
    scan_k<<<NBLK, 256>>>();
    // 3) GEMM0 + fused LN/ReLU -> g_m; appended blocks do CSR fill
    mma_k<0><<<tiles + FILLB, 256, SM_TOTAL>>>(pA0h, pA0l, pBh + 0 * 32768, pBl + 0 * 32768,
                                               bm, ln_g, ln_b, p_m, nullptr, nullptr,
                                               nullptr, nullptr, src, dst, E, N, rowsTot);
    // 4) CSR aggregation: fills A0[:,128:256], A2[:,128:256], g_conv
    agg_k<<<(rowsTot * 32 + 255) / 256, 256>>>(h, pA0h, pA0l, pA2h, pA2l, p_conv, rowsTot);
    // 5) GEMM1 -> g_std (+ split into A2 first half)
    mma_k<1><<<tiles, 256, SM_TOTAL>>>(pA0h, pA0l, pBh + 1 * 32768, pBl + 1 * 32768, b_sage,
                                       nullptr, nullptr, p_std, pA2h, pA2l, nullptr, nullptr,
                                       nullptr, nullptr, 0, N, rowsTot);
    // 6) GEMM2 + fused sigmoid/blend -> out
    mma_k<2><<<tiles, 256, SM_TOTAL>>>(pA2h, pA2l, pBh + 2 * 32768, pBl + 2 * 32768, bg,
                                       nullptr, nullptr, out, nullptr, nullptr, p_std, p_conv,
                                       nullptr, nullptr, 0, N, rowsTot);
}